// round 8
// baseline (speedup 1.0000x reference)
#include <cuda_runtime.h>
#include <math.h>
#include <stdint.h>

// ---------------- problem constants ----------------
#define B_      1024
#define NTOK    54
#define WIN     49
#define NP      5
#define NH      12
#define HD      32
#define DIM     384
#define QKVD    1152
#define NWIN    64
#define WH      7
#define WW      7
#define SCALE   0.17677669529663687f
#define MTOK    (B_*NTOK)       // 55296
#define KDIM    384

// ---------------- scratch ----------------
__device__ float d_qkv[(size_t)MTOK * QKVD];
__device__ float d_att[(size_t)MTOK * DIM];      // tf32-rounded attention output
__device__ float d_xr[(size_t)MTOK * DIM];       // tf32-rounded x
__device__ float d_wq[QKVD * DIM];               // tf32-rounded qkv_w
__device__ float d_wp[DIM * DIM];                // tf32-rounded proj_w
__device__ float d_bm[NH * NWIN * 64 * 64];      // combined bias+mask, padded

__device__ __forceinline__ uint32_t f2tf32(float f) {
    uint32_t r;
    asm("cvt.rna.tf32.f32 %0, %1;" : "=r"(r) : "f"(f));
    return r;
}

// ---------------- prepass: round arrays to tf32 ----------------
__global__ void round_tf32(const float* __restrict__ in, float* __restrict__ out, int n4) {
    int i = blockIdx.x * blockDim.x + threadIdx.x;
    if (i >= n4) return;
    float4 v = reinterpret_cast<const float4*>(in)[i];
    v.x = __uint_as_float(f2tf32(v.x));
    v.y = __uint_as_float(f2tf32(v.y));
    v.z = __uint_as_float(f2tf32(v.z));
    v.w = __uint_as_float(f2tf32(v.w));
    reinterpret_cast<float4*>(out)[i] = v;
}

// ---------------- prepass: combined bias+mask table ----------------
__global__ void bm_kernel(const float* __restrict__ rpb, const float* __restrict__ mask) {
    int idx = blockIdx.x * blockDim.x + threadIdx.x;
    const int total = NH * NWIN * 64 * 64;
    if (idx >= total) return;
    int c  = idx & 63;
    int r  = (idx >> 6) & 63;
    int wv = (idx >> 12) & 63;
    int h  = idx >> 18;
    float v = 0.f;
    if (r < NTOK) {
        if (c < NTOK) {
            if (r >= NP && c >= NP) {
                int i = r - NP, j = c - NP;
                int ih = i / WW, iw = i % WW;
                int jh = j / WW, jw = j % WW;
                int rpi = (ih - jh + WH - 1) * (2 * WW - 1) + (iw - jw + WW - 1);
                v = rpb[rpi * NH + h] + mask[wv * WIN * WIN + i * WIN + j];
            }
        } else {
            v = -1e30f;
        }
    }
    d_bm[idx] = v;
}

// ================= tf32 mma.sync GEMM, BK=32, reg-level pipelining =======
// C[M,N] = A[M,384] @ W[N,384]^T + bias ; inputs pre-rounded to tf32
#define BM 128
#define BN 128
#define BK 32
#define PADK 36
#define TILEF   (BM * PADK)          // floats per matrix per buffer (4608)
#define ABYTES  (TILEF * 4)          // 18432
#define SMEM_GEMM (4 * ABYTES)       // 73728

__device__ __forceinline__ void cp16(uint32_t smem, const float* g) {
    asm volatile("cp.async.cg.shared.global [%0], [%1], 16;\n" :: "r"(smem), "l"(g));
}

__device__ __forceinline__ void mma_tf32(float* c,
    uint32_t a0, uint32_t a1, uint32_t a2, uint32_t a3,
    uint32_t b0, uint32_t b1)
{
    asm volatile(
        "mma.sync.aligned.m16n8k8.row.col.f32.tf32.tf32.f32 "
        "{%0,%1,%2,%3}, {%4,%5,%6,%7}, {%8,%9}, {%0,%1,%2,%3};\n"
        : "+f"(c[0]), "+f"(c[1]), "+f"(c[2]), "+f"(c[3])
        : "r"(a0), "r"(a1), "r"(a2), "r"(a3), "r"(b0), "r"(b1));
}

template<int N>
__device__ __forceinline__ void tgemm_body(
    const float* __restrict__ A, const float* __restrict__ W,
    const float* __restrict__ bias, float* __restrict__ C, int K)
{
    extern __shared__ __align__(16) float smem[];
    float* As = smem;                   // [2][TILEF]
    float* Bs = smem + 2 * TILEF;       // [2][TILEF]

    const int tid  = threadIdx.x;
    const int warp = tid >> 5, lane = tid & 31;
    const int g    = lane >> 2, tg = lane & 3;
    const int wm   = warp & 1;
    const int wn   = warp >> 1;
    const int m0   = blockIdx.y * BM;
    const int n0   = blockIdx.x * BN;

    // producer: row = tid/2 (0..127), kq = (tid&1)*16 ; 4 float4 per matrix
    const int lr = tid >> 1;
    const int kq = (tid & 1) * 16;
    const float* Ag = A + (size_t)(m0 + lr) * K + kq;
    const float* Wg = W + (size_t)(n0 + lr) * K + kq;

    uint32_t sAb = (uint32_t)__cvta_generic_to_shared(As);
    uint32_t sBb = (uint32_t)__cvta_generic_to_shared(Bs);
    const uint32_t sAo = sAb + (lr * PADK + kq) * 4;
    const uint32_t sBo = sBb + (lr * PADK + kq) * 4;

    float acc[4][4][4];
    #pragma unroll
    for (int i = 0; i < 4; i++)
        #pragma unroll
        for (int j = 0; j < 4; j++)
            #pragma unroll
            for (int c = 0; c < 4; c++) acc[i][j][c] = 0.f;

    const int nt = K / BK;       // 12

    // prologue: tile 0 -> buffer 0
    #pragma unroll
    for (int j = 0; j < 4; j++) {
        cp16(sAo + j * 16, Ag + j * 4);
        cp16(sBo + j * 16, Wg + j * 4);
    }
    asm volatile("cp.async.commit_group;\n");

    uint32_t af[2][4][4], bf[2][4][2];

    for (int t = 0; t < nt; t++) {
        asm volatile("cp.async.wait_group 0;\n");
        __syncthreads();
        const int buf = t & 1;
        if (t + 1 < nt) {
            const float* ap = Ag + (size_t)(t + 1) * BK;
            const float* wp = Wg + (size_t)(t + 1) * BK;
            const uint32_t bo = (buf ^ 1) * ABYTES;
            #pragma unroll
            for (int j = 0; j < 4; j++) {
                cp16(sAo + bo + j * 16, ap + j * 4);
                cp16(sBo + bo + j * 16, wp + j * 4);
            }
            asm volatile("cp.async.commit_group;\n");
        }

        const float* __restrict__ Asb = As + buf * TILEF;
        const float* __restrict__ Bsb = Bs + buf * TILEF;

        // load fragments for s = 0
        {
            const int kb = 0;
            #pragma unroll
            for (int i = 0; i < 4; i++) {
                const int rb = wm * 64 + i * 16;
                af[0][i][0] = __float_as_uint(Asb[(rb + g)     * PADK + kb + tg]);
                af[0][i][1] = __float_as_uint(Asb[(rb + g + 8) * PADK + kb + tg]);
                af[0][i][2] = __float_as_uint(Asb[(rb + g)     * PADK + kb + tg + 4]);
                af[0][i][3] = __float_as_uint(Asb[(rb + g + 8) * PADK + kb + tg + 4]);
            }
            #pragma unroll
            for (int j = 0; j < 4; j++) {
                const int cb = wn * 32 + j * 8;
                bf[0][j][0] = __float_as_uint(Bsb[(cb + g) * PADK + kb + tg]);
                bf[0][j][1] = __float_as_uint(Bsb[(cb + g) * PADK + kb + tg + 4]);
            }
        }

        #pragma unroll
        for (int s = 0; s < 4; s++) {
            const int cur = s & 1;
            // prefetch fragments for s+1 while MMAs of s issue
            if (s < 3) {
                const int nxt = cur ^ 1;
                const int kb = (s + 1) * 8;
                #pragma unroll
                for (int i = 0; i < 4; i++) {
                    const int rb = wm * 64 + i * 16;
                    af[nxt][i][0] = __float_as_uint(Asb[(rb + g)     * PADK + kb + tg]);
                    af[nxt][i][1] = __float_as_uint(Asb[(rb + g + 8) * PADK + kb + tg]);
                    af[nxt][i][2] = __float_as_uint(Asb[(rb + g)     * PADK + kb + tg + 4]);
                    af[nxt][i][3] = __float_as_uint(Asb[(rb + g + 8) * PADK + kb + tg + 4]);
                }
                #pragma unroll
                for (int j = 0; j < 4; j++) {
                    const int cb = wn * 32 + j * 8;
                    bf[nxt][j][0] = __float_as_uint(Bsb[(cb + g) * PADK + kb + tg]);
                    bf[nxt][j][1] = __float_as_uint(Bsb[(cb + g) * PADK + kb + tg + 4]);
                }
            }
            #pragma unroll
            for (int i = 0; i < 4; i++)
                #pragma unroll
                for (int j = 0; j < 4; j++)
                    mma_tf32(acc[i][j],
                             af[cur][i][0], af[cur][i][1], af[cur][i][2], af[cur][i][3],
                             bf[cur][j][0], bf[cur][j][1]);
        }
        __syncthreads();
    }

    // epilogue: add bias, store
    #pragma unroll
    for (int i = 0; i < 4; i++) {
        const int rb = m0 + wm * 64 + i * 16 + g;
        #pragma unroll
        for (int j = 0; j < 4; j++) {
            const int cb = n0 + wn * 32 + j * 8 + 2 * tg;
            const float b0v = bias[cb], b1v = bias[cb + 1];
            float2 v0, v1;
            v0.x = acc[i][j][0] + b0v;  v0.y = acc[i][j][1] + b1v;
            v1.x = acc[i][j][2] + b0v;  v1.y = acc[i][j][3] + b1v;
            *reinterpret_cast<float2*>(&C[(size_t)rb * N + cb])       = v0;
            *reinterpret_cast<float2*>(&C[(size_t)(rb + 8) * N + cb]) = v1;
        }
    }
}

__global__ __launch_bounds__(256, 2) void k_qkv(const float* __restrict__ b)
{
    tgemm_body<QKVD>(d_xr, d_wq, b, d_qkv, KDIM);
}

__global__ __launch_bounds__(256, 2) void k_proj(const float* __restrict__ b,
                                                 float* __restrict__ out)
{
    tgemm_body<DIM>(d_att, d_wp, b, out, KDIM);
}

// ================= tensor-core attention: one block (128 thr) per (b,h) ==
#define SQH 0
#define SKH 2304
#define SVT 4608
#define SQL 6784
#define SKL (6784 + 2304)
#define SPP 6784
#define SMTOT 11392

__global__ __launch_bounds__(128) void attn_tc()
{
    __shared__ uint32_t sm[SMTOT];

    const int b = blockIdx.x / NH;
    const int h = blockIdx.x % NH;
    const int tid = threadIdx.x;

    const float* base = d_qkv + (size_t)b * NTOK * QKVD + h * HD;

    for (int idx = tid; idx < 64 * 32; idx += 128) {
        const int r = idx >> 5, d = idx & 31;
        float qv = 0.f, kv = 0.f, vv = 0.f;
        if (r < NTOK) {
            qv = base[r * QKVD + d] * SCALE;
            kv = base[r * QKVD + DIM + d];
            vv = base[r * QKVD + 2 * DIM + d];
        }
        const uint32_t qhi = f2tf32(qv);
        const uint32_t khi = f2tf32(kv);
        const float qlo = qv - __uint_as_float(qhi);
        const float klo = kv - __uint_as_float(khi);
        sm[SQH + r * 36 + d] = qhi;
        sm[SKH + r * 36 + d] = khi;
        sm[SQL + r * 36 + d] = f2tf32(qlo);
        sm[SKL + r * 36 + d] = f2tf32(klo);
        sm[SVT + d * 68 + r] = f2tf32(vv);
    }
    __syncthreads();

    const int w = tid >> 5, lane = tid & 31;
    const int g = lane >> 2, tg = lane & 3;
    const int r0 = w * 16 + g;

    float s[8][4];
    #pragma unroll
    for (int j = 0; j < 8; j++)
        #pragma unroll
        for (int c = 0; c < 4; c++) s[j][c] = 0.f;

    #pragma unroll
    for (int kk = 0; kk < 4; kk++) {
        const int ko = kk * 8;
        const uint32_t a0 = sm[SQH + r0 * 36 + ko + tg];
        const uint32_t a1 = sm[SQH + (r0 + 8) * 36 + ko + tg];
        const uint32_t a2 = sm[SQH + r0 * 36 + ko + tg + 4];
        const uint32_t a3 = sm[SQH + (r0 + 8) * 36 + ko + tg + 4];
        const uint32_t l0 = sm[SQL + r0 * 36 + ko + tg];
        const uint32_t l1 = sm[SQL + (r0 + 8) * 36 + ko + tg];
        const uint32_t l2 = sm[SQL + r0 * 36 + ko + tg + 4];
        const uint32_t l3 = sm[SQL + (r0 + 8) * 36 + ko + tg + 4];
        #pragma unroll
        for (int j = 0; j < 8; j++) {
            const int kr = j * 8 + g;
            const uint32_t b0 = sm[SKH + kr * 36 + ko + tg];
            const uint32_t b1 = sm[SKH + kr * 36 + ko + tg + 4];
            const uint32_t c0 = sm[SKL + kr * 36 + ko + tg];
            const uint32_t c1 = sm[SKL + kr * 36 + ko + tg + 4];
            mma_tf32(s[j], a0, a1, a2, a3, b0, b1);
            mma_tf32(s[j], l0, l1, l2, l3, b0, b1);
            mma_tf32(s[j], a0, a1, a2, a3, c0, c1);
        }
    }

    const float* bmp = d_bm + ((size_t)(h * NWIN + (b & (NWIN - 1)))) * 64 * 64;
    #pragma unroll
    for (int j = 0; j < 8; j++) {
        const float2 t0 = *reinterpret_cast<const float2*>(&bmp[r0 * 64 + j * 8 + 2 * tg]);
        const float2 t1 = *reinterpret_cast<const float2*>(&bmp[(r0 + 8) * 64 + j * 8 + 2 * tg]);
        s[j][0] += t0.x;  s[j][1] += t0.y;
        s[j][2] += t1.x;  s[j][3] += t1.y;
    }

    float m0 = -1e30f, m1 = -1e30f;
    #pragma unroll
    for (int j = 0; j < 8; j++) {
        m0 = fmaxf(m0, fmaxf(s[j][0], s[j][1]));
        m1 = fmaxf(m1, fmaxf(s[j][2], s[j][3]));
    }
    m0 = fmaxf(m0, __shfl_xor_sync(0xffffffffu, m0, 1));
    m0 = fmaxf(m0, __shfl_xor_sync(0xffffffffu, m0, 2));
    m1 = fmaxf(m1, __shfl_xor_sync(0xffffffffu, m1, 1));
    m1 = fmaxf(m1, __shfl_xor_sync(0xffffffffu, m1, 2));

    float sum0 = 0.f, sum1 = 0.f;
    #pragma unroll
    for (int j = 0; j < 8; j++) {
        s[j][0] = __expf(s[j][0] - m0);
        s[j][1] = __expf(s[j][1] - m0);
        s[j][2] = __expf(s[j][2] - m1);
        s[j][3] = __expf(s[j][3] - m1);
        sum0 += s[j][0] + s[j][1];
        sum1 += s[j][2] + s[j][3];
    }
    sum0 += __shfl_xor_sync(0xffffffffu, sum0, 1);
    sum0 += __shfl_xor_sync(0xffffffffu, sum0, 2);
    sum1 += __shfl_xor_sync(0xffffffffu, sum1, 1);
    sum1 += __shfl_xor_sync(0xffffffffu, sum1, 2);
    const float inv0 = 1.f / sum0;
    const float inv1 = 1.f / sum1;

    __syncthreads();   // QL/KL reads done before PP overwrites

    #pragma unroll
    for (int j = 0; j < 8; j++) {
        uint2 p0, p1;
        p0.x = f2tf32(s[j][0] * inv0);  p0.y = f2tf32(s[j][1] * inv0);
        p1.x = f2tf32(s[j][2] * inv1);  p1.y = f2tf32(s[j][3] * inv1);
        *reinterpret_cast<uint2*>(&sm[SPP + r0 * 68 + j * 8 + 2 * tg])       = p0;
        *reinterpret_cast<uint2*>(&sm[SPP + (r0 + 8) * 68 + j * 8 + 2 * tg]) = p1;
    }
    __syncwarp();

    float o[4][4];
    #pragma unroll
    for (int n = 0; n < 4; n++)
        #pragma unroll
        for (int c = 0; c < 4; c++) o[n][c] = 0.f;

    #pragma unroll
    for (int kk = 0; kk < 8; kk++) {
        const int ko = kk * 8;
        const uint32_t a0 = sm[SPP + r0 * 68 + ko + tg];
        const uint32_t a1 = sm[SPP + (r0 + 8) * 68 + ko + tg];
        const uint32_t a2 = sm[SPP + r0 * 68 + ko + tg + 4];
        const uint32_t a3 = sm[SPP + (r0 + 8) * 68 + ko + tg + 4];
        #pragma unroll
        for (int n = 0; n < 4; n++) {
            const int vr = n * 8 + g;
            const uint32_t b0 = sm[SVT + vr * 68 + ko + tg];
            const uint32_t b1 = sm[SVT + vr * 68 + ko + tg + 4];
            mma_tf32(o[n], a0, a1, a2, a3, b0, b1);
        }
    }

    if (r0 < NTOK) {
        float* op = d_att + ((size_t)b * NTOK + r0) * DIM + h * HD;
        #pragma unroll
        for (int n = 0; n < 4; n++) {
            float2 v;
            v.x = __uint_as_float(f2tf32(o[n][0]));
            v.y = __uint_as_float(f2tf32(o[n][1]));
            *reinterpret_cast<float2*>(&op[n * 8 + 2 * tg]) = v;
        }
    }
    if (r0 + 8 < NTOK) {
        float* op = d_att + ((size_t)b * NTOK + r0 + 8) * DIM + h * HD;
        #pragma unroll
        for (int n = 0; n < 4; n++) {
            float2 v;
            v.x = __uint_as_float(f2tf32(o[n][2]));
            v.y = __uint_as_float(f2tf32(o[n][3]));
            *reinterpret_cast<float2*>(&op[n * 8 + 2 * tg]) = v;
        }
    }
}

// ---------------- launch ----------------
extern "C" void kernel_launch(void* const* d_in, const int* in_sizes, int n_in,
                              void* d_out, int out_size)
{
    const float* x      = (const float*)d_in[0];
    const float* mask   = (const float*)d_in[1];
    const float* qkv_w  = (const float*)d_in[2];
    const float* qkv_b  = (const float*)d_in[3];
    const float* proj_w = (const float*)d_in[4];
    const float* proj_b = (const float*)d_in[5];
    const float* rpb    = (const float*)d_in[6];
    float* out          = (float*)d_out;

    cudaFuncSetAttribute(k_qkv,  cudaFuncAttributeMaxDynamicSharedMemorySize, SMEM_GEMM);
    cudaFuncSetAttribute(k_proj, cudaFuncAttributeMaxDynamicSharedMemorySize, SMEM_GEMM);

    float *xr, *wq, *wp;
    cudaGetSymbolAddress((void**)&xr, d_xr);
    cudaGetSymbolAddress((void**)&wq, d_wq);
    cudaGetSymbolAddress((void**)&wp, d_wp);

    {
        int n4 = (MTOK * DIM) / 4;
        round_tf32<<<(n4 + 255) / 256, 256>>>(x, xr, n4);
        n4 = (QKVD * DIM) / 4;
        round_tf32<<<(n4 + 255) / 256, 256>>>(qkv_w, wq, n4);
        n4 = (DIM * DIM) / 4;
        round_tf32<<<(n4 + 255) / 256, 256>>>(proj_w, wp, n4);
        const int total = NH * NWIN * 64 * 64;
        bm_kernel<<<(total + 255) / 256, 256>>>(rpb, mask);
    }

    {   // QKV: (55296 x 384) @ (1152 x 384)^T
        dim3 grid(QKVD / BN, MTOK / BM);
        k_qkv<<<grid, 256, SMEM_GEMM>>>(qkv_b);
    }

    attn_tc<<<B_ * NH, 128>>>();

    {   // proj: (55296 x 384) @ (384 x 384)^T
        dim3 grid(DIM / BN, MTOK / BM);
        k_proj<<<grid, 256, SMEM_GEMM>>>(proj_b, out);
    }
}

// round 9
// speedup vs baseline: 1.1647x; 1.1647x over previous
#include <cuda_runtime.h>
#include <math.h>
#include <stdint.h>

// ---------------- problem constants ----------------
#define B_      1024
#define NTOK    54
#define WIN     49
#define NP      5
#define NH      12
#define HD      32
#define DIM     384
#define QKVD    1152
#define NWIN    64
#define WH      7
#define WW      7
#define SCALE   0.17677669529663687f
#define MTOK    (B_*NTOK)       // 55296
#define KDIM    384

// ---------------- scratch ----------------
__device__ float d_qkv[(size_t)MTOK * QKVD];
__device__ float d_att[(size_t)MTOK * DIM];      // tf32-rounded attention output
__device__ float d_xr[(size_t)MTOK * DIM];       // tf32-rounded x
__device__ float d_wq[QKVD * DIM];               // tf32-rounded qkv_w
__device__ float d_wp[DIM * DIM];                // tf32-rounded proj_w
__device__ float d_bm[NH * NWIN * 64 * 64];      // combined bias+mask, padded

__device__ __forceinline__ uint32_t f2tf32(float f) {
    uint32_t r;
    asm("cvt.rna.tf32.f32 %0, %1;" : "=r"(r) : "f"(f));
    return r;
}

// ---------------- prepass: round arrays to tf32 ----------------
__global__ void round_tf32(const float* __restrict__ in, float* __restrict__ out, int n4) {
    int i = blockIdx.x * blockDim.x + threadIdx.x;
    if (i >= n4) return;
    float4 v = reinterpret_cast<const float4*>(in)[i];
    v.x = __uint_as_float(f2tf32(v.x));
    v.y = __uint_as_float(f2tf32(v.y));
    v.z = __uint_as_float(f2tf32(v.z));
    v.w = __uint_as_float(f2tf32(v.w));
    reinterpret_cast<float4*>(out)[i] = v;
}

// ---------------- prepass: combined bias+mask table ----------------
__global__ void bm_kernel(const float* __restrict__ rpb, const float* __restrict__ mask) {
    int idx = blockIdx.x * blockDim.x + threadIdx.x;
    const int total = NH * NWIN * 64 * 64;
    if (idx >= total) return;
    int c  = idx & 63;
    int r  = (idx >> 6) & 63;
    int wv = (idx >> 12) & 63;
    int h  = idx >> 18;
    float v = 0.f;
    if (r < NTOK) {
        if (c < NTOK) {
            if (r >= NP && c >= NP) {
                int i = r - NP, j = c - NP;
                int ih = i / WW, iw = i % WW;
                int jh = j / WW, jw = j % WW;
                int rpi = (ih - jh + WH - 1) * (2 * WW - 1) + (iw - jw + WW - 1);
                v = rpb[rpi * NH + h] + mask[wv * WIN * WIN + i * WIN + j];
            }
        } else {
            v = -1e30f;
        }
    }
    d_bm[idx] = v;
}

// ================= tf32 mma.sync GEMM, BK=16, 3-stage cp.async ===========
// C[M,N] = A[M,384] @ W[N,384]^T + bias ; inputs pre-rounded to tf32
#define BM 128
#define BN 128
#define BK 16
#define PAD_K 20
#define AFLOATS (BM * PAD_K)           // 2560
#define ABYTES  (AFLOATS * 4)          // 10240
#define STAGEB  (2 * ABYTES)           // 20480 (A + B per stage)
#define SMEM_GEMM (3 * STAGEB)         // 61440

__device__ __forceinline__ void cp16(uint32_t smem, const float* g) {
    asm volatile("cp.async.cg.shared.global [%0], [%1], 16;\n" :: "r"(smem), "l"(g));
}

__device__ __forceinline__ void mma_tf32(float* c,
    uint32_t a0, uint32_t a1, uint32_t a2, uint32_t a3,
    uint32_t b0, uint32_t b1)
{
    asm volatile(
        "mma.sync.aligned.m16n8k8.row.col.f32.tf32.tf32.f32 "
        "{%0,%1,%2,%3}, {%4,%5,%6,%7}, {%8,%9}, {%0,%1,%2,%3};\n"
        : "+f"(c[0]), "+f"(c[1]), "+f"(c[2]), "+f"(c[3])
        : "r"(a0), "r"(a1), "r"(a2), "r"(a3), "r"(b0), "r"(b1));
}

template<int N>
__device__ __forceinline__ void tgemm_body(
    const float* __restrict__ A, const float* __restrict__ W,
    const float* __restrict__ bias, float* __restrict__ C, int K)
{
    extern __shared__ __align__(16) float smem[];

    const int tid  = threadIdx.x;
    const int warp = tid >> 5, lane = tid & 31;
    const int g    = lane >> 2, tg = lane & 3;
    const int wm   = warp & 1;
    const int wn   = warp >> 1;
    const int m0   = blockIdx.y * BM;
    const int n0   = blockIdx.x * BN;

    // producer indexing: rows lr and lr+64, k-cols lk..lk+3
    const int lr = tid >> 2;
    const int lk = (tid & 3) * 4;
    const float* Ag = A + (size_t)(m0 + lr) * K + lk;
    const float* Wg = W + (size_t)(n0 + lr) * K + lk;

    const uint32_t sbase = (uint32_t)__cvta_generic_to_shared(smem);
    const uint32_t aoff0 = (lr * PAD_K + lk) * 4;
    const uint32_t aoff1 = ((lr + 64) * PAD_K + lk) * 4;

    float acc[4][4][4];
    #pragma unroll
    for (int i = 0; i < 4; i++)
        #pragma unroll
        for (int j = 0; j < 4; j++)
            #pragma unroll
            for (int c = 0; c < 4; c++) acc[i][j][c] = 0.f;

    const int nt = K / BK;     // 24

    // prologue: stage tiles 0 and 1
    #pragma unroll
    for (int p = 0; p < 2; p++) {
        const float* ap = Ag + (size_t)p * BK;
        const float* wp = Wg + (size_t)p * BK;
        const uint32_t sA = sbase + p * STAGEB;
        const uint32_t sB = sA + ABYTES;
        cp16(sA + aoff0, ap);
        cp16(sA + aoff1, ap + (size_t)64 * K);
        cp16(sB + aoff0, wp);
        cp16(sB + aoff1, wp + (size_t)64 * K);
        asm volatile("cp.async.commit_group;\n");
    }

    int stage = 0;           // stage of tile t
    int nstage = 2;          // stage where tile t+2 will go

    for (int t = 0; t < nt; t++) {
        if (t < nt - 1) asm volatile("cp.async.wait_group 1;\n");
        else            asm volatile("cp.async.wait_group 0;\n");
        __syncthreads();     // tile t ready for all; all warps done with stage's previous tenant

        if (t + 2 < nt) {
            const float* ap = Ag + (size_t)(t + 2) * BK;
            const float* wp = Wg + (size_t)(t + 2) * BK;
            const uint32_t sA = sbase + nstage * STAGEB;
            const uint32_t sB = sA + ABYTES;
            cp16(sA + aoff0, ap);
            cp16(sA + aoff1, ap + (size_t)64 * K);
            cp16(sB + aoff0, wp);
            cp16(sB + aoff1, wp + (size_t)64 * K);
            asm volatile("cp.async.commit_group;\n");
        }

        const float* __restrict__ Asb = smem + stage * (STAGEB / 4);
        const float* __restrict__ Bsb = Asb + AFLOATS;

        #pragma unroll
        for (int s = 0; s < 2; s++) {
            const int kb = s * 8;
            uint32_t af[4][4], bfr[4][2];
            #pragma unroll
            for (int i = 0; i < 4; i++) {
                const int rb = wm * 64 + i * 16;
                af[i][0] = __float_as_uint(Asb[(rb + g)     * PAD_K + kb + tg]);
                af[i][1] = __float_as_uint(Asb[(rb + g + 8) * PAD_K + kb + tg]);
                af[i][2] = __float_as_uint(Asb[(rb + g)     * PAD_K + kb + tg + 4]);
                af[i][3] = __float_as_uint(Asb[(rb + g + 8) * PAD_K + kb + tg + 4]);
            }
            #pragma unroll
            for (int j = 0; j < 4; j++) {
                const int cb = wn * 32 + j * 8;
                bfr[j][0] = __float_as_uint(Bsb[(cb + g) * PAD_K + kb + tg]);
                bfr[j][1] = __float_as_uint(Bsb[(cb + g) * PAD_K + kb + tg + 4]);
            }
            #pragma unroll
            for (int i = 0; i < 4; i++)
                #pragma unroll
                for (int j = 0; j < 4; j++)
                    mma_tf32(acc[i][j], af[i][0], af[i][1], af[i][2], af[i][3],
                             bfr[j][0], bfr[j][1]);
        }

        stage  = (stage  == 2) ? 0 : stage  + 1;
        nstage = (nstage == 2) ? 0 : nstage + 1;
    }

    // epilogue: add bias, store
    #pragma unroll
    for (int i = 0; i < 4; i++) {
        const int rb = m0 + wm * 64 + i * 16 + g;
        #pragma unroll
        for (int j = 0; j < 4; j++) {
            const int cb = n0 + wn * 32 + j * 8 + 2 * tg;
            const float b0v = bias[cb], b1v = bias[cb + 1];
            float2 v0, v1;
            v0.x = acc[i][j][0] + b0v;  v0.y = acc[i][j][1] + b1v;
            v1.x = acc[i][j][2] + b0v;  v1.y = acc[i][j][3] + b1v;
            *reinterpret_cast<float2*>(&C[(size_t)rb * N + cb])       = v0;
            *reinterpret_cast<float2*>(&C[(size_t)(rb + 8) * N + cb]) = v1;
        }
    }
}

__global__ __launch_bounds__(256, 2) void k_qkv(const float* __restrict__ b)
{
    tgemm_body<QKVD>(d_xr, d_wq, b, d_qkv, KDIM);
}

__global__ __launch_bounds__(256, 2) void k_proj(const float* __restrict__ b,
                                                 float* __restrict__ out)
{
    tgemm_body<DIM>(d_att, d_wp, b, out, KDIM);
}

// ================= tensor-core attention: one block (128 thr) per (b,h) ==
#define SQH 0
#define SKH 2304
#define SVT 4608
#define SQL 6784
#define SKL (6784 + 2304)
#define SPP 6784
#define SMTOT 11392

__global__ __launch_bounds__(128) void attn_tc()
{
    __shared__ uint32_t sm[SMTOT];

    const int b = blockIdx.x / NH;
    const int h = blockIdx.x % NH;
    const int tid = threadIdx.x;

    const float* base = d_qkv + (size_t)b * NTOK * QKVD + h * HD;

    for (int idx = tid; idx < 64 * 32; idx += 128) {
        const int r = idx >> 5, d = idx & 31;
        float qv = 0.f, kv = 0.f, vv = 0.f;
        if (r < NTOK) {
            qv = base[r * QKVD + d] * SCALE;
            kv = base[r * QKVD + DIM + d];
            vv = base[r * QKVD + 2 * DIM + d];
        }
        const uint32_t qhi = f2tf32(qv);
        const uint32_t khi = f2tf32(kv);
        const float qlo = qv - __uint_as_float(qhi);
        const float klo = kv - __uint_as_float(khi);
        sm[SQH + r * 36 + d] = qhi;
        sm[SKH + r * 36 + d] = khi;
        sm[SQL + r * 36 + d] = f2tf32(qlo);
        sm[SKL + r * 36 + d] = f2tf32(klo);
        sm[SVT + d * 68 + r] = f2tf32(vv);
    }
    __syncthreads();

    const int w = tid >> 5, lane = tid & 31;
    const int g = lane >> 2, tg = lane & 3;
    const int r0 = w * 16 + g;

    float s[8][4];
    #pragma unroll
    for (int j = 0; j < 8; j++)
        #pragma unroll
        for (int c = 0; c < 4; c++) s[j][c] = 0.f;

    #pragma unroll
    for (int kk = 0; kk < 4; kk++) {
        const int ko = kk * 8;
        const uint32_t a0 = sm[SQH + r0 * 36 + ko + tg];
        const uint32_t a1 = sm[SQH + (r0 + 8) * 36 + ko + tg];
        const uint32_t a2 = sm[SQH + r0 * 36 + ko + tg + 4];
        const uint32_t a3 = sm[SQH + (r0 + 8) * 36 + ko + tg + 4];
        const uint32_t l0 = sm[SQL + r0 * 36 + ko + tg];
        const uint32_t l1 = sm[SQL + (r0 + 8) * 36 + ko + tg];
        const uint32_t l2 = sm[SQL + r0 * 36 + ko + tg + 4];
        const uint32_t l3 = sm[SQL + (r0 + 8) * 36 + ko + tg + 4];
        #pragma unroll
        for (int j = 0; j < 8; j++) {
            const int kr = j * 8 + g;
            const uint32_t b0 = sm[SKH + kr * 36 + ko + tg];
            const uint32_t b1 = sm[SKH + kr * 36 + ko + tg + 4];
            const uint32_t c0 = sm[SKL + kr * 36 + ko + tg];
            const uint32_t c1 = sm[SKL + kr * 36 + ko + tg + 4];
            mma_tf32(s[j], a0, a1, a2, a3, b0, b1);
            mma_tf32(s[j], l0, l1, l2, l3, b0, b1);
            mma_tf32(s[j], a0, a1, a2, a3, c0, c1);
        }
    }

    const float* bmp = d_bm + ((size_t)(h * NWIN + (b & (NWIN - 1)))) * 64 * 64;
    #pragma unroll
    for (int j = 0; j < 8; j++) {
        const float2 t0 = *reinterpret_cast<const float2*>(&bmp[r0 * 64 + j * 8 + 2 * tg]);
        const float2 t1 = *reinterpret_cast<const float2*>(&bmp[(r0 + 8) * 64 + j * 8 + 2 * tg]);
        s[j][0] += t0.x;  s[j][1] += t0.y;
        s[j][2] += t1.x;  s[j][3] += t1.y;
    }

    float m0 = -1e30f, m1 = -1e30f;
    #pragma unroll
    for (int j = 0; j < 8; j++) {
        m0 = fmaxf(m0, fmaxf(s[j][0], s[j][1]));
        m1 = fmaxf(m1, fmaxf(s[j][2], s[j][3]));
    }
    m0 = fmaxf(m0, __shfl_xor_sync(0xffffffffu, m0, 1));
    m0 = fmaxf(m0, __shfl_xor_sync(0xffffffffu, m0, 2));
    m1 = fmaxf(m1, __shfl_xor_sync(0xffffffffu, m1, 1));
    m1 = fmaxf(m1, __shfl_xor_sync(0xffffffffu, m1, 2));

    float sum0 = 0.f, sum1 = 0.f;
    #pragma unroll
    for (int j = 0; j < 8; j++) {
        s[j][0] = __expf(s[j][0] - m0);
        s[j][1] = __expf(s[j][1] - m0);
        s[j][2] = __expf(s[j][2] - m1);
        s[j][3] = __expf(s[j][3] - m1);
        sum0 += s[j][0] + s[j][1];
        sum1 += s[j][2] + s[j][3];
    }
    sum0 += __shfl_xor_sync(0xffffffffu, sum0, 1);
    sum0 += __shfl_xor_sync(0xffffffffu, sum0, 2);
    sum1 += __shfl_xor_sync(0xffffffffu, sum1, 1);
    sum1 += __shfl_xor_sync(0xffffffffu, sum1, 2);
    const float inv0 = 1.f / sum0;
    const float inv1 = 1.f / sum1;

    __syncthreads();   // QL/KL reads done before PP overwrites

    #pragma unroll
    for (int j = 0; j < 8; j++) {
        uint2 p0, p1;
        p0.x = f2tf32(s[j][0] * inv0);  p0.y = f2tf32(s[j][1] * inv0);
        p1.x = f2tf32(s[j][2] * inv1);  p1.y = f2tf32(s[j][3] * inv1);
        *reinterpret_cast<uint2*>(&sm[SPP + r0 * 68 + j * 8 + 2 * tg])       = p0;
        *reinterpret_cast<uint2*>(&sm[SPP + (r0 + 8) * 68 + j * 8 + 2 * tg]) = p1;
    }
    __syncwarp();

    float o[4][4];
    #pragma unroll
    for (int n = 0; n < 4; n++)
        #pragma unroll
        for (int c = 0; c < 4; c++) o[n][c] = 0.f;

    #pragma unroll
    for (int kk = 0; kk < 8; kk++) {
        const int ko = kk * 8;
        const uint32_t a0 = sm[SPP + r0 * 68 + ko + tg];
        const uint32_t a1 = sm[SPP + (r0 + 8) * 68 + ko + tg];
        const uint32_t a2 = sm[SPP + r0 * 68 + ko + tg + 4];
        const uint32_t a3 = sm[SPP + (r0 + 8) * 68 + ko + tg + 4];
        #pragma unroll
        for (int n = 0; n < 4; n++) {
            const int vr = n * 8 + g;
            const uint32_t b0 = sm[SVT + vr * 68 + ko + tg];
            const uint32_t b1 = sm[SVT + vr * 68 + ko + tg + 4];
            mma_tf32(o[n], a0, a1, a2, a3, b0, b1);
        }
    }

    if (r0 < NTOK) {
        float* op = d_att + ((size_t)b * NTOK + r0) * DIM + h * HD;
        #pragma unroll
        for (int n = 0; n < 4; n++) {
            float2 v;
            v.x = __uint_as_float(f2tf32(o[n][0]));
            v.y = __uint_as_float(f2tf32(o[n][1]));
            *reinterpret_cast<float2*>(&op[n * 8 + 2 * tg]) = v;
        }
    }
    if (r0 + 8 < NTOK) {
        float* op = d_att + ((size_t)b * NTOK + r0 + 8) * DIM + h * HD;
        #pragma unroll
        for (int n = 0; n < 4; n++) {
            float2 v;
            v.x = __uint_as_float(f2tf32(o[n][2]));
            v.y = __uint_as_float(f2tf32(o[n][3]));
            *reinterpret_cast<float2*>(&op[n * 8 + 2 * tg]) = v;
        }
    }
}

// ---------------- launch ----------------
extern "C" void kernel_launch(void* const* d_in, const int* in_sizes, int n_in,
                              void* d_out, int out_size)
{
    const float* x      = (const float*)d_in[0];
    const float* mask   = (const float*)d_in[1];
    const float* qkv_w  = (const float*)d_in[2];
    const float* qkv_b  = (const float*)d_in[3];
    const float* proj_w = (const float*)d_in[4];
    const float* proj_b = (const float*)d_in[5];
    const float* rpb    = (const float*)d_in[6];
    float* out          = (float*)d_out;

    cudaFuncSetAttribute(k_qkv,  cudaFuncAttributeMaxDynamicSharedMemorySize, SMEM_GEMM);
    cudaFuncSetAttribute(k_proj, cudaFuncAttributeMaxDynamicSharedMemorySize, SMEM_GEMM);

    float *xr, *wq, *wp;
    cudaGetSymbolAddress((void**)&xr, d_xr);
    cudaGetSymbolAddress((void**)&wq, d_wq);
    cudaGetSymbolAddress((void**)&wp, d_wp);

    {
        int n4 = (MTOK * DIM) / 4;
        round_tf32<<<(n4 + 255) / 256, 256>>>(x, xr, n4);
        n4 = (QKVD * DIM) / 4;
        round_tf32<<<(n4 + 255) / 256, 256>>>(qkv_w, wq, n4);
        n4 = (DIM * DIM) / 4;
        round_tf32<<<(n4 + 255) / 256, 256>>>(proj_w, wp, n4);
        const int total = NH * NWIN * 64 * 64;
        bm_kernel<<<(total + 255) / 256, 256>>>(rpb, mask);
    }

    {   // QKV: (55296 x 384) @ (1152 x 384)^T
        dim3 grid(QKVD / BN, MTOK / BM);
        k_qkv<<<grid, 256, SMEM_GEMM>>>(qkv_b);
    }

    attn_tc<<<B_ * NH, 128>>>();

    {   // proj: (55296 x 384) @ (384 x 384)^T
        dim3 grid(DIM / BN, MTOK / BM);
        k_proj<<<grid, 256, SMEM_GEMM>>>(proj_b, out);
    }
}

// round 10
// speedup vs baseline: 1.7125x; 1.4703x over previous
#include <cuda_runtime.h>
#include <cuda_fp16.h>
#include <math.h>
#include <stdint.h>

// ---------------- problem constants ----------------
#define B_      1024
#define NTOK    54
#define WIN     49
#define NP      5
#define NH      12
#define HD      32
#define DIM     384
#define QKVD    1152
#define NWIN    64
#define WH      7
#define WW      7
#define SCALE   0.17677669529663687f
#define MTOK    (B_*NTOK)       // 55296
#define KDIM    384

// ---------------- scratch ----------------
__device__ float  d_qkv[(size_t)MTOK * QKVD];    // fp32 qkv (attention input)
__device__ __half d_att[(size_t)MTOK * DIM];     // fp16 attention output (proj A)
__device__ __half d_xh[(size_t)MTOK * DIM];      // fp16 x
__device__ __half d_wqh[QKVD * DIM];             // fp16 qkv_w
__device__ __half d_wph[DIM * DIM];              // fp16 proj_w
__device__ float  d_bm[NH * NWIN * 64 * 64];     // combined bias+mask, padded

__device__ __forceinline__ uint32_t f2tf32(float f) {
    uint32_t r;
    asm("cvt.rna.tf32.f32 %0, %1;" : "=r"(r) : "f"(f));
    return r;
}

// ---------------- prepass: convert arrays to fp16 ----------------
__global__ void to_half(const float* __restrict__ in, __half* __restrict__ out, int n4) {
    int i = blockIdx.x * blockDim.x + threadIdx.x;
    if (i >= n4) return;
    float4 v = reinterpret_cast<const float4*>(in)[i];
    __half2 h0 = __floats2half2_rn(v.x, v.y);
    __half2 h1 = __floats2half2_rn(v.z, v.w);
    reinterpret_cast<__half2*>(out)[i * 2]     = h0;
    reinterpret_cast<__half2*>(out)[i * 2 + 1] = h1;
}

// ---------------- prepass: combined bias+mask table ----------------
__global__ void bm_kernel(const float* __restrict__ rpb, const float* __restrict__ mask) {
    int idx = blockIdx.x * blockDim.x + threadIdx.x;
    const int total = NH * NWIN * 64 * 64;
    if (idx >= total) return;
    int c  = idx & 63;
    int r  = (idx >> 6) & 63;
    int wv = (idx >> 12) & 63;
    int h  = idx >> 18;
    float v = 0.f;
    if (r < NTOK) {
        if (c < NTOK) {
            if (r >= NP && c >= NP) {
                int i = r - NP, j = c - NP;
                int ih = i / WW, iw = i % WW;
                int jh = j / WW, jw = j % WW;
                int rpi = (ih - jh + WH - 1) * (2 * WW - 1) + (iw - jw + WW - 1);
                v = rpb[rpi * NH + h] + mask[wv * WIN * WIN + i * WIN + j];
            }
        } else {
            v = -1e30f;
        }
    }
    d_bm[idx] = v;
}

// ================= fp16 mma.sync GEMM, BK=32, ldmatrix, 3-stage ==========
// C[M,N] = A[M,384] @ W[N,384]^T + bias ; A,W fp16 in gmem, fp32 accumulate
#define BM 128
#define BN 128
#define BK 32                      // k-elements (halfs) per tile
#define RS 40                      // row stride in halfs (80 B) -> conflict-free LDSM
#define ABYTES  (BM * RS * 2)      // 10240
#define STAGEB  (2 * ABYTES)       // 20480 (A + B per stage)
#define SMEM_GEMM (3 * STAGEB)     // 61440

__device__ __forceinline__ void cp16(uint32_t smem, const __half* g) {
    asm volatile("cp.async.cg.shared.global [%0], [%1], 16;\n" :: "r"(smem), "l"(g));
}

__device__ __forceinline__ void ldsm_x4(uint32_t* r, uint32_t addr) {
    asm volatile("ldmatrix.sync.aligned.m8n8.x4.shared.b16 {%0,%1,%2,%3}, [%4];"
        : "=r"(r[0]), "=r"(r[1]), "=r"(r[2]), "=r"(r[3]) : "r"(addr));
}

__device__ __forceinline__ void mma_f16(float* c, const uint32_t* a,
                                        uint32_t b0, uint32_t b1)
{
    asm volatile(
        "mma.sync.aligned.m16n8k16.row.col.f32.f16.f16.f32 "
        "{%0,%1,%2,%3}, {%4,%5,%6,%7}, {%8,%9}, {%0,%1,%2,%3};\n"
        : "+f"(c[0]), "+f"(c[1]), "+f"(c[2]), "+f"(c[3])
        : "r"(a[0]), "r"(a[1]), "r"(a[2]), "r"(a[3]), "r"(b0), "r"(b1));
}

template<int N>
__device__ __forceinline__ void tgemm_body(
    const __half* __restrict__ A, const __half* __restrict__ W,
    const float* __restrict__ bias, float* __restrict__ C, int K)
{
    extern __shared__ __align__(16) char smem[];

    const int tid  = threadIdx.x;
    const int warp = tid >> 5, lane = tid & 31;
    const int g    = lane >> 2, tg = lane & 3;
    const int wm   = warp & 1;
    const int wn   = warp >> 1;
    const int m0   = blockIdx.y * BM;
    const int n0   = blockIdx.x * BN;

    // ---- producer indexing: row = tid/2, 32 B (2 x 16 B) per matrix ----
    const int lr = tid >> 1;
    const int hk = (tid & 1) * 16;           // half offset within the 32-half row
    const __half* Ag = A + (size_t)(m0 + lr) * K + hk;
    const __half* Wg = W + (size_t)(n0 + lr) * K + hk;

    const uint32_t sbase = (uint32_t)__cvta_generic_to_shared(smem);
    const uint32_t poff  = (lr * RS + hk) * 2;   // byte offset in tile

    // ---- consumer ldmatrix address offsets (bytes within tile) ----
    const int l7  = lane & 7;
    const int lb3 = (lane >> 3) & 1;
    const int lb4 = lane >> 4;
    uint32_t aoffA[4], boffB[2];
    #pragma unroll
    for (int i = 0; i < 4; i++) {
        const int row = wm * 64 + i * 16 + l7 + 8 * lb3;
        aoffA[i] = (row * RS + 8 * lb4) * 2;
    }
    #pragma unroll
    for (int p = 0; p < 2; p++) {
        const int row = wn * 32 + p * 16 + l7 + 8 * lb4;
        boffB[p] = (row * RS + 8 * lb3) * 2;
    }

    float acc[4][4][4];
    #pragma unroll
    for (int i = 0; i < 4; i++)
        #pragma unroll
        for (int j = 0; j < 4; j++)
            #pragma unroll
            for (int c = 0; c < 4; c++) acc[i][j][c] = 0.f;

    const int nt = K / BK;     // 12

    // prologue: stage tiles 0 and 1
    #pragma unroll
    for (int p = 0; p < 2; p++) {
        const __half* ap = Ag + (size_t)p * BK;
        const __half* wp = Wg + (size_t)p * BK;
        const uint32_t sA = sbase + p * STAGEB + poff;
        const uint32_t sB = sA + ABYTES;
        cp16(sA, ap);       cp16(sA + 16, ap + 8);
        cp16(sB, wp);       cp16(sB + 16, wp + 8);
        asm volatile("cp.async.commit_group;\n");
    }

    int stage = 0;
    int nstage = 2;

    for (int t = 0; t < nt; t++) {
        if (t < nt - 1) asm volatile("cp.async.wait_group 1;\n");
        else            asm volatile("cp.async.wait_group 0;\n");
        __syncthreads();

        if (t + 2 < nt) {
            const __half* ap = Ag + (size_t)(t + 2) * BK;
            const __half* wp = Wg + (size_t)(t + 2) * BK;
            const uint32_t sA = sbase + nstage * STAGEB + poff;
            const uint32_t sB = sA + ABYTES;
            cp16(sA, ap);       cp16(sA + 16, ap + 8);
            cp16(sB, wp);       cp16(sB + 16, wp + 8);
            asm volatile("cp.async.commit_group;\n");
        }

        const uint32_t aS = sbase + stage * STAGEB;
        const uint32_t bS = aS + ABYTES;

        #pragma unroll
        for (int s = 0; s < 2; s++) {
            const uint32_t ks = s * 32;          // 16 halfs = 32 bytes
            uint32_t af[4][4], bfr[4][2];
            #pragma unroll
            for (int i = 0; i < 4; i++)
                ldsm_x4(af[i], aS + aoffA[i] + ks);
            #pragma unroll
            for (int p = 0; p < 2; p++) {
                uint32_t br[4];
                ldsm_x4(br, bS + boffB[p] + ks);
                bfr[2 * p][0]     = br[0];  bfr[2 * p][1]     = br[1];
                bfr[2 * p + 1][0] = br[2];  bfr[2 * p + 1][1] = br[3];
            }
            #pragma unroll
            for (int i = 0; i < 4; i++)
                #pragma unroll
                for (int j = 0; j < 4; j++)
                    mma_f16(acc[i][j], af[i], bfr[j][0], bfr[j][1]);
        }

        stage  = (stage  == 2) ? 0 : stage  + 1;
        nstage = (nstage == 2) ? 0 : nstage + 1;
    }

    // epilogue: add bias, store fp32
    #pragma unroll
    for (int i = 0; i < 4; i++) {
        const int rb = m0 + wm * 64 + i * 16 + g;
        #pragma unroll
        for (int j = 0; j < 4; j++) {
            const int cb = n0 + wn * 32 + j * 8 + 2 * tg;
            const float b0v = bias[cb], b1v = bias[cb + 1];
            float2 v0, v1;
            v0.x = acc[i][j][0] + b0v;  v0.y = acc[i][j][1] + b1v;
            v1.x = acc[i][j][2] + b0v;  v1.y = acc[i][j][3] + b1v;
            *reinterpret_cast<float2*>(&C[(size_t)rb * N + cb])       = v0;
            *reinterpret_cast<float2*>(&C[(size_t)(rb + 8) * N + cb]) = v1;
        }
    }
}

__global__ __launch_bounds__(256, 2) void k_qkv(const float* __restrict__ b)
{
    tgemm_body<QKVD>(d_xh, d_wqh, b, d_qkv, KDIM);
}

__global__ __launch_bounds__(256, 2) void k_proj(const float* __restrict__ b,
                                                 float* __restrict__ out)
{
    tgemm_body<DIM>(d_att, d_wph, b, out, KDIM);
}

// ================= tensor-core attention: one block (128 thr) per (b,h) ==
#define SQH 0
#define SKH 2304
#define SVT 4608
#define SQL 6784
#define SKL (6784 + 2304)
#define SPP 6784
#define SMTOT 11392

__device__ __forceinline__ void mma_tf32(float* c,
    uint32_t a0, uint32_t a1, uint32_t a2, uint32_t a3,
    uint32_t b0, uint32_t b1)
{
    asm volatile(
        "mma.sync.aligned.m16n8k8.row.col.f32.tf32.tf32.f32 "
        "{%0,%1,%2,%3}, {%4,%5,%6,%7}, {%8,%9}, {%0,%1,%2,%3};\n"
        : "+f"(c[0]), "+f"(c[1]), "+f"(c[2]), "+f"(c[3])
        : "r"(a0), "r"(a1), "r"(a2), "r"(a3), "r"(b0), "r"(b1));
}

__global__ __launch_bounds__(128) void attn_tc()
{
    __shared__ uint32_t sm[SMTOT];

    const int b = blockIdx.x / NH;
    const int h = blockIdx.x % NH;
    const int tid = threadIdx.x;

    const float* base = d_qkv + (size_t)b * NTOK * QKVD + h * HD;

    for (int idx = tid; idx < 64 * 32; idx += 128) {
        const int r = idx >> 5, d = idx & 31;
        float qv = 0.f, kv = 0.f, vv = 0.f;
        if (r < NTOK) {
            qv = base[r * QKVD + d] * SCALE;
            kv = base[r * QKVD + DIM + d];
            vv = base[r * QKVD + 2 * DIM + d];
        }
        const uint32_t qhi = f2tf32(qv);
        const uint32_t khi = f2tf32(kv);
        const float qlo = qv - __uint_as_float(qhi);
        const float klo = kv - __uint_as_float(khi);
        sm[SQH + r * 36 + d] = qhi;
        sm[SKH + r * 36 + d] = khi;
        sm[SQL + r * 36 + d] = f2tf32(qlo);
        sm[SKL + r * 36 + d] = f2tf32(klo);
        sm[SVT + d * 68 + r] = f2tf32(vv);
    }
    __syncthreads();

    const int w = tid >> 5, lane = tid & 31;
    const int g = lane >> 2, tg = lane & 3;
    const int r0 = w * 16 + g;

    float s[8][4];
    #pragma unroll
    for (int j = 0; j < 8; j++)
        #pragma unroll
        for (int c = 0; c < 4; c++) s[j][c] = 0.f;

    #pragma unroll
    for (int kk = 0; kk < 4; kk++) {
        const int ko = kk * 8;
        const uint32_t a0 = sm[SQH + r0 * 36 + ko + tg];
        const uint32_t a1 = sm[SQH + (r0 + 8) * 36 + ko + tg];
        const uint32_t a2 = sm[SQH + r0 * 36 + ko + tg + 4];
        const uint32_t a3 = sm[SQH + (r0 + 8) * 36 + ko + tg + 4];
        const uint32_t l0 = sm[SQL + r0 * 36 + ko + tg];
        const uint32_t l1 = sm[SQL + (r0 + 8) * 36 + ko + tg];
        const uint32_t l2 = sm[SQL + r0 * 36 + ko + tg + 4];
        const uint32_t l3 = sm[SQL + (r0 + 8) * 36 + ko + tg + 4];
        #pragma unroll
        for (int j = 0; j < 8; j++) {
            const int kr = j * 8 + g;
            const uint32_t b0 = sm[SKH + kr * 36 + ko + tg];
            const uint32_t b1 = sm[SKH + kr * 36 + ko + tg + 4];
            const uint32_t c0 = sm[SKL + kr * 36 + ko + tg];
            const uint32_t c1 = sm[SKL + kr * 36 + ko + tg + 4];
            mma_tf32(s[j], a0, a1, a2, a3, b0, b1);
            mma_tf32(s[j], l0, l1, l2, l3, b0, b1);
            mma_tf32(s[j], a0, a1, a2, a3, c0, c1);
        }
    }

    const float* bmp = d_bm + ((size_t)(h * NWIN + (b & (NWIN - 1)))) * 64 * 64;
    #pragma unroll
    for (int j = 0; j < 8; j++) {
        const float2 t0 = *reinterpret_cast<const float2*>(&bmp[r0 * 64 + j * 8 + 2 * tg]);
        const float2 t1 = *reinterpret_cast<const float2*>(&bmp[(r0 + 8) * 64 + j * 8 + 2 * tg]);
        s[j][0] += t0.x;  s[j][1] += t0.y;
        s[j][2] += t1.x;  s[j][3] += t1.y;
    }

    float m0 = -1e30f, m1 = -1e30f;
    #pragma unroll
    for (int j = 0; j < 8; j++) {
        m0 = fmaxf(m0, fmaxf(s[j][0], s[j][1]));
        m1 = fmaxf(m1, fmaxf(s[j][2], s[j][3]));
    }
    m0 = fmaxf(m0, __shfl_xor_sync(0xffffffffu, m0, 1));
    m0 = fmaxf(m0, __shfl_xor_sync(0xffffffffu, m0, 2));
    m1 = fmaxf(m1, __shfl_xor_sync(0xffffffffu, m1, 1));
    m1 = fmaxf(m1, __shfl_xor_sync(0xffffffffu, m1, 2));

    float sum0 = 0.f, sum1 = 0.f;
    #pragma unroll
    for (int j = 0; j < 8; j++) {
        s[j][0] = __expf(s[j][0] - m0);
        s[j][1] = __expf(s[j][1] - m0);
        s[j][2] = __expf(s[j][2] - m1);
        s[j][3] = __expf(s[j][3] - m1);
        sum0 += s[j][0] + s[j][1];
        sum1 += s[j][2] + s[j][3];
    }
    sum0 += __shfl_xor_sync(0xffffffffu, sum0, 1);
    sum0 += __shfl_xor_sync(0xffffffffu, sum0, 2);
    sum1 += __shfl_xor_sync(0xffffffffu, sum1, 1);
    sum1 += __shfl_xor_sync(0xffffffffu, sum1, 2);
    const float inv0 = 1.f / sum0;
    const float inv1 = 1.f / sum1;

    __syncthreads();   // QL/KL reads done before PP overwrites

    #pragma unroll
    for (int j = 0; j < 8; j++) {
        uint2 p0, p1;
        p0.x = f2tf32(s[j][0] * inv0);  p0.y = f2tf32(s[j][1] * inv0);
        p1.x = f2tf32(s[j][2] * inv1);  p1.y = f2tf32(s[j][3] * inv1);
        *reinterpret_cast<uint2*>(&sm[SPP + r0 * 68 + j * 8 + 2 * tg])       = p0;
        *reinterpret_cast<uint2*>(&sm[SPP + (r0 + 8) * 68 + j * 8 + 2 * tg]) = p1;
    }
    __syncwarp();

    float o[4][4];
    #pragma unroll
    for (int n = 0; n < 4; n++)
        #pragma unroll
        for (int c = 0; c < 4; c++) o[n][c] = 0.f;

    #pragma unroll
    for (int kk = 0; kk < 8; kk++) {
        const int ko = kk * 8;
        const uint32_t a0 = sm[SPP + r0 * 68 + ko + tg];
        const uint32_t a1 = sm[SPP + (r0 + 8) * 68 + ko + tg];
        const uint32_t a2 = sm[SPP + r0 * 68 + ko + tg + 4];
        const uint32_t a3 = sm[SPP + (r0 + 8) * 68 + ko + tg + 4];
        #pragma unroll
        for (int n = 0; n < 4; n++) {
            const int vr = n * 8 + g;
            const uint32_t b0 = sm[SVT + vr * 68 + ko + tg];
            const uint32_t b1 = sm[SVT + vr * 68 + ko + tg + 4];
            mma_tf32(o[n], a0, a1, a2, a3, b0, b1);
        }
    }

    // store fp16 for the proj GEMM
    if (r0 < NTOK) {
        __half* op = d_att + ((size_t)b * NTOK + r0) * DIM + h * HD;
        #pragma unroll
        for (int n = 0; n < 4; n++)
            *reinterpret_cast<__half2*>(&op[n * 8 + 2 * tg]) =
                __floats2half2_rn(o[n][0], o[n][1]);
    }
    if (r0 + 8 < NTOK) {
        __half* op = d_att + ((size_t)b * NTOK + r0 + 8) * DIM + h * HD;
        #pragma unroll
        for (int n = 0; n < 4; n++)
            *reinterpret_cast<__half2*>(&op[n * 8 + 2 * tg]) =
                __floats2half2_rn(o[n][2], o[n][3]);
    }
}

// ---------------- launch ----------------
extern "C" void kernel_launch(void* const* d_in, const int* in_sizes, int n_in,
                              void* d_out, int out_size)
{
    const float* x      = (const float*)d_in[0];
    const float* mask   = (const float*)d_in[1];
    const float* qkv_w  = (const float*)d_in[2];
    const float* qkv_b  = (const float*)d_in[3];
    const float* proj_w = (const float*)d_in[4];
    const float* proj_b = (const float*)d_in[5];
    const float* rpb    = (const float*)d_in[6];
    float* out          = (float*)d_out;

    cudaFuncSetAttribute(k_qkv,  cudaFuncAttributeMaxDynamicSharedMemorySize, SMEM_GEMM);
    cudaFuncSetAttribute(k_proj, cudaFuncAttributeMaxDynamicSharedMemorySize, SMEM_GEMM);

    __half *xh, *wqh, *wph;
    cudaGetSymbolAddress((void**)&xh,  d_xh);
    cudaGetSymbolAddress((void**)&wqh, d_wqh);
    cudaGetSymbolAddress((void**)&wph, d_wph);

    {
        int n4 = (MTOK * DIM) / 4;
        to_half<<<(n4 + 255) / 256, 256>>>(x, xh, n4);
        n4 = (QKVD * DIM) / 4;
        to_half<<<(n4 + 255) / 256, 256>>>(qkv_w, wqh, n4);
        n4 = (DIM * DIM) / 4;
        to_half<<<(n4 + 255) / 256, 256>>>(proj_w, wph, n4);
        const int total = NH * NWIN * 64 * 64;
        bm_kernel<<<(total + 255) / 256, 256>>>(rpb, mask);
    }

    {   // QKV: (55296 x 384) @ (1152 x 384)^T
        dim3 grid(QKVD / BN, MTOK / BM);
        k_qkv<<<grid, 256, SMEM_GEMM>>>(qkv_b);
    }

    attn_tc<<<B_ * NH, 128>>>();

    {   // proj: (55296 x 384) @ (384 x 384)^T
        dim3 grid(DIM / BN, MTOK / BM);
        k_proj<<<grid, 256, SMEM_GEMM>>>(proj_b, out);
    }
}

// round 11
// speedup vs baseline: 1.8852x; 1.1009x over previous
#include <cuda_runtime.h>
#include <cuda_fp16.h>
#include <math.h>
#include <stdint.h>

// ---------------- problem constants ----------------
#define B_      1024
#define NTOK    54
#define WIN     49
#define NP      5
#define NH      12
#define HD      32
#define DIM     384
#define QKVD    1152
#define NWIN    64
#define WH      7
#define WW      7
#define SCALE   0.17677669529663687f
#define MTOK    (B_*NTOK)       // 55296
#define KDIM    384

// ---------------- scratch ----------------
__device__ float  d_qkv[(size_t)MTOK * QKVD];    // fp32 qkv (attention input)
__device__ __half d_att[(size_t)MTOK * DIM];     // fp16 attention output (proj A)
__device__ __half d_xh[(size_t)MTOK * DIM];      // fp16 x
__device__ __half d_wqh[QKVD * DIM];             // fp16 qkv_w
__device__ __half d_wph[DIM * DIM];              // fp16 proj_w
__device__ float  d_bm[NH * NWIN * 64 * 64];     // combined bias+mask, padded

// ---------------- prepass: convert arrays to fp16 ----------------
__global__ void to_half(const float* __restrict__ in, __half* __restrict__ out, int n4) {
    int i = blockIdx.x * blockDim.x + threadIdx.x;
    if (i >= n4) return;
    float4 v = reinterpret_cast<const float4*>(in)[i];
    __half2 h0 = __floats2half2_rn(v.x, v.y);
    __half2 h1 = __floats2half2_rn(v.z, v.w);
    reinterpret_cast<__half2*>(out)[i * 2]     = h0;
    reinterpret_cast<__half2*>(out)[i * 2 + 1] = h1;
}

// ---------------- prepass: combined bias+mask table ----------------
__global__ void bm_kernel(const float* __restrict__ rpb, const float* __restrict__ mask) {
    int idx = blockIdx.x * blockDim.x + threadIdx.x;
    const int total = NH * NWIN * 64 * 64;
    if (idx >= total) return;
    int c  = idx & 63;
    int r  = (idx >> 6) & 63;
    int wv = (idx >> 12) & 63;
    int h  = idx >> 18;
    float v = 0.f;
    if (r < NTOK) {
        if (c < NTOK) {
            if (r >= NP && c >= NP) {
                int i = r - NP, j = c - NP;
                int ih = i / WW, iw = i % WW;
                int jh = j / WW, jw = j % WW;
                int rpi = (ih - jh + WH - 1) * (2 * WW - 1) + (iw - jw + WW - 1);
                v = rpb[rpi * NH + h] + mask[wv * WIN * WIN + i * WIN + j];
            }
        } else {
            v = -1e30f;
        }
    }
    d_bm[idx] = v;
}

// ================= shared MMA/ldmatrix helpers =================
__device__ __forceinline__ void cp16(uint32_t smem, const __half* g) {
    asm volatile("cp.async.cg.shared.global [%0], [%1], 16;\n" :: "r"(smem), "l"(g));
}

__device__ __forceinline__ void ldsm_x4(uint32_t* r, uint32_t addr) {
    asm volatile("ldmatrix.sync.aligned.m8n8.x4.shared.b16 {%0,%1,%2,%3}, [%4];"
        : "=r"(r[0]), "=r"(r[1]), "=r"(r[2]), "=r"(r[3]) : "r"(addr));
}

__device__ __forceinline__ void mma_f16(float* c, const uint32_t* a,
                                        uint32_t b0, uint32_t b1)
{
    asm volatile(
        "mma.sync.aligned.m16n8k16.row.col.f32.f16.f16.f32 "
        "{%0,%1,%2,%3}, {%4,%5,%6,%7}, {%8,%9}, {%0,%1,%2,%3};\n"
        : "+f"(c[0]), "+f"(c[1]), "+f"(c[2]), "+f"(c[3])
        : "r"(a[0]), "r"(a[1]), "r"(a[2]), "r"(a[3]), "r"(b0), "r"(b1));
}

// ================= fp16 mma.sync GEMM, BK=32, ldmatrix, 3-stage ==========
#define BM 128
#define BN 128
#define BK 32
#define RS 40                      // row stride in halfs (80 B)
#define ABYTES  (BM * RS * 2)      // 10240
#define STAGEB  (2 * ABYTES)       // 20480
#define SMEM_GEMM (3 * STAGEB)     // 61440

template<int N>
__device__ __forceinline__ void tgemm_body(
    const __half* __restrict__ A, const __half* __restrict__ W,
    const float* __restrict__ bias, float* __restrict__ C, int K)
{
    extern __shared__ __align__(16) char smem[];

    const int tid  = threadIdx.x;
    const int warp = tid >> 5, lane = tid & 31;
    const int g    = lane >> 2, tg = lane & 3;
    const int wm   = warp & 1;
    const int wn   = warp >> 1;
    const int m0   = blockIdx.y * BM;
    const int n0   = blockIdx.x * BN;

    const int lr = tid >> 1;
    const int hk = (tid & 1) * 16;
    const __half* Ag = A + (size_t)(m0 + lr) * K + hk;
    const __half* Wg = W + (size_t)(n0 + lr) * K + hk;

    const uint32_t sbase = (uint32_t)__cvta_generic_to_shared(smem);
    const uint32_t poff  = (lr * RS + hk) * 2;

    const int l7  = lane & 7;
    const int lb3 = (lane >> 3) & 1;
    const int lb4 = lane >> 4;
    uint32_t aoffA[4], boffB[2];
    #pragma unroll
    for (int i = 0; i < 4; i++) {
        const int row = wm * 64 + i * 16 + l7 + 8 * lb3;
        aoffA[i] = (row * RS + 8 * lb4) * 2;
    }
    #pragma unroll
    for (int p = 0; p < 2; p++) {
        const int row = wn * 32 + p * 16 + l7 + 8 * lb4;
        boffB[p] = (row * RS + 8 * lb3) * 2;
    }

    float acc[4][4][4];
    #pragma unroll
    for (int i = 0; i < 4; i++)
        #pragma unroll
        for (int j = 0; j < 4; j++)
            #pragma unroll
            for (int c = 0; c < 4; c++) acc[i][j][c] = 0.f;

    const int nt = K / BK;

    #pragma unroll
    for (int p = 0; p < 2; p++) {
        const __half* ap = Ag + (size_t)p * BK;
        const __half* wp = Wg + (size_t)p * BK;
        const uint32_t sA = sbase + p * STAGEB + poff;
        const uint32_t sB = sA + ABYTES;
        cp16(sA, ap);       cp16(sA + 16, ap + 8);
        cp16(sB, wp);       cp16(sB + 16, wp + 8);
        asm volatile("cp.async.commit_group;\n");
    }

    int stage = 0;
    int nstage = 2;

    for (int t = 0; t < nt; t++) {
        if (t < nt - 1) asm volatile("cp.async.wait_group 1;\n");
        else            asm volatile("cp.async.wait_group 0;\n");
        __syncthreads();

        if (t + 2 < nt) {
            const __half* ap = Ag + (size_t)(t + 2) * BK;
            const __half* wp = Wg + (size_t)(t + 2) * BK;
            const uint32_t sA = sbase + nstage * STAGEB + poff;
            const uint32_t sB = sA + ABYTES;
            cp16(sA, ap);       cp16(sA + 16, ap + 8);
            cp16(sB, wp);       cp16(sB + 16, wp + 8);
            asm volatile("cp.async.commit_group;\n");
        }

        const uint32_t aS = sbase + stage * STAGEB;
        const uint32_t bS = aS + ABYTES;

        #pragma unroll
        for (int s = 0; s < 2; s++) {
            const uint32_t ks = s * 32;
            uint32_t af[4][4], bfr[4][2];
            #pragma unroll
            for (int i = 0; i < 4; i++)
                ldsm_x4(af[i], aS + aoffA[i] + ks);
            #pragma unroll
            for (int p = 0; p < 2; p++) {
                uint32_t br[4];
                ldsm_x4(br, bS + boffB[p] + ks);
                bfr[2 * p][0]     = br[0];  bfr[2 * p][1]     = br[1];
                bfr[2 * p + 1][0] = br[2];  bfr[2 * p + 1][1] = br[3];
            }
            #pragma unroll
            for (int i = 0; i < 4; i++)
                #pragma unroll
                for (int j = 0; j < 4; j++)
                    mma_f16(acc[i][j], af[i], bfr[j][0], bfr[j][1]);
        }

        stage  = (stage  == 2) ? 0 : stage  + 1;
        nstage = (nstage == 2) ? 0 : nstage + 1;
    }

    #pragma unroll
    for (int i = 0; i < 4; i++) {
        const int rb = m0 + wm * 64 + i * 16 + g;
        #pragma unroll
        for (int j = 0; j < 4; j++) {
            const int cb = n0 + wn * 32 + j * 8 + 2 * tg;
            const float b0v = bias[cb], b1v = bias[cb + 1];
            float2 v0, v1;
            v0.x = acc[i][j][0] + b0v;  v0.y = acc[i][j][1] + b1v;
            v1.x = acc[i][j][2] + b0v;  v1.y = acc[i][j][3] + b1v;
            *reinterpret_cast<float2*>(&C[(size_t)rb * N + cb])       = v0;
            *reinterpret_cast<float2*>(&C[(size_t)(rb + 8) * N + cb]) = v1;
        }
    }
}

__global__ __launch_bounds__(256, 2) void k_qkv(const float* __restrict__ b)
{
    tgemm_body<QKVD>(d_xh, d_wqh, b, d_qkv, KDIM);
}

__global__ __launch_bounds__(256, 2) void k_proj(const float* __restrict__ b,
                                                 float* __restrict__ out)
{
    tgemm_body<DIM>(d_att, d_wph, b, out, KDIM);
}

// ================= fp16 tensor-core attention: one block (128 thr) per (b,h)
// smem byte offsets (half regions):
//   QH [64][40]h @ 0       (5120 B)
//   QL [64][40]h @ 5120
//   KH [64][40]h @ 10240
//   KL [64][40]h @ 15360
//   VT [32][72]h @ 20480   (4608 B)   V transposed [d][key]
//   PP [64][72]h @ 25088   (9216 B)
#define AQH 0u
#define AQL 5120u
#define AKH 10240u
#define AKL 15360u
#define AVT 20480u
#define APP 25088u
#define ATT_SMEM 34304

__global__ __launch_bounds__(128) void attn_tc()
{
    __shared__ __align__(16) char smraw[ATT_SMEM];
    __half* smh = reinterpret_cast<__half*>(smraw);
    const uint32_t sb = (uint32_t)__cvta_generic_to_shared(smraw);

    const int b = blockIdx.x / NH;
    const int h = blockIdx.x % NH;
    const int tid = threadIdx.x;

    const float* base = d_qkv + (size_t)b * NTOK * QKVD + h * HD;

    // ---- load fp32 qkv, split q/k into fp16 hi/lo, v to fp16, VT transposed
    for (int idx = tid; idx < 64 * 32; idx += 128) {
        const int r = idx >> 5, d = idx & 31;
        float qv = 0.f, kv = 0.f, vv = 0.f;
        if (r < NTOK) {
            qv = base[r * QKVD + d] * SCALE;
            kv = base[r * QKVD + DIM + d];
            vv = base[r * QKVD + 2 * DIM + d];
        }
        const __half qh = __float2half_rn(qv);
        const __half kh = __float2half_rn(kv);
        const __half ql = __float2half_rn(qv - __half2float(qh));
        const __half kl = __float2half_rn(kv - __half2float(kh));
        smh[(AQH >> 1) + r * 40 + d] = qh;
        smh[(AQL >> 1) + r * 40 + d] = ql;
        smh[(AKH >> 1) + r * 40 + d] = kh;
        smh[(AKL >> 1) + r * 40 + d] = kl;
        smh[(AVT >> 1) + d * 72 + r] = __float2half_rn(vv);
    }
    __syncthreads();

    const int w = tid >> 5, lane = tid & 31;
    const int g = lane >> 2, tg = lane & 3;
    const int r0 = w * 16 + g;

    const int l7  = lane & 7;
    const int lb3 = (lane >> 3) & 1;
    const int lb4 = lane >> 4;

    // ldmatrix offsets
    const uint32_t aoffQ = ((w * 16 + l7 + 8 * lb3) * 40 + 8 * lb4) * 2;
    uint32_t boffK[4];
    #pragma unroll
    for (int j2 = 0; j2 < 4; j2++)
        boffK[j2] = ((j2 * 16 + l7 + 8 * lb4) * 40 + 8 * lb3) * 2;
    const uint32_t poffP = ((w * 16 + l7 + 8 * lb3) * 72 + 8 * lb4) * 2;
    uint32_t voffV[2];
    #pragma unroll
    for (int n2 = 0; n2 < 2; n2++)
        voffV[n2] = ((n2 * 16 + l7 + 8 * lb4) * 72 + 8 * lb3) * 2;

    // ---- QK^T with fp16 hi/lo (3 MMAs per tile) ----
    float s[8][4];
    #pragma unroll
    for (int j = 0; j < 8; j++)
        #pragma unroll
        for (int c = 0; c < 4; c++) s[j][c] = 0.f;

    #pragma unroll
    for (int kc = 0; kc < 2; kc++) {
        const uint32_t ks = kc * 32;      // 16 halfs
        uint32_t aH[4], aL[4];
        ldsm_x4(aH, sb + AQH + aoffQ + ks);
        ldsm_x4(aL, sb + AQL + aoffQ + ks);
        #pragma unroll
        for (int j2 = 0; j2 < 4; j2++) {
            uint32_t bH[4], bL[4];
            ldsm_x4(bH, sb + AKH + boffK[j2] + ks);
            ldsm_x4(bL, sb + AKL + boffK[j2] + ks);
            mma_f16(s[2 * j2],     aH, bH[0], bH[1]);
            mma_f16(s[2 * j2],     aL, bH[0], bH[1]);
            mma_f16(s[2 * j2],     aH, bL[0], bL[1]);
            mma_f16(s[2 * j2 + 1], aH, bH[2], bH[3]);
            mma_f16(s[2 * j2 + 1], aL, bH[2], bH[3]);
            mma_f16(s[2 * j2 + 1], aH, bL[2], bL[3]);
        }
    }

    // ---- bias+mask add ----
    const float* bmp = d_bm + ((size_t)(h * NWIN + (b & (NWIN - 1)))) * 64 * 64;
    #pragma unroll
    for (int j = 0; j < 8; j++) {
        const float2 t0 = *reinterpret_cast<const float2*>(&bmp[r0 * 64 + j * 8 + 2 * tg]);
        const float2 t1 = *reinterpret_cast<const float2*>(&bmp[(r0 + 8) * 64 + j * 8 + 2 * tg]);
        s[j][0] += t0.x;  s[j][1] += t0.y;
        s[j][2] += t1.x;  s[j][3] += t1.y;
    }

    // ---- softmax ----
    float m0 = -1e30f, m1 = -1e30f;
    #pragma unroll
    for (int j = 0; j < 8; j++) {
        m0 = fmaxf(m0, fmaxf(s[j][0], s[j][1]));
        m1 = fmaxf(m1, fmaxf(s[j][2], s[j][3]));
    }
    m0 = fmaxf(m0, __shfl_xor_sync(0xffffffffu, m0, 1));
    m0 = fmaxf(m0, __shfl_xor_sync(0xffffffffu, m0, 2));
    m1 = fmaxf(m1, __shfl_xor_sync(0xffffffffu, m1, 1));
    m1 = fmaxf(m1, __shfl_xor_sync(0xffffffffu, m1, 2));

    float sum0 = 0.f, sum1 = 0.f;
    #pragma unroll
    for (int j = 0; j < 8; j++) {
        s[j][0] = __expf(s[j][0] - m0);
        s[j][1] = __expf(s[j][1] - m0);
        s[j][2] = __expf(s[j][2] - m1);
        s[j][3] = __expf(s[j][3] - m1);
        sum0 += s[j][0] + s[j][1];
        sum1 += s[j][2] + s[j][3];
    }
    sum0 += __shfl_xor_sync(0xffffffffu, sum0, 1);
    sum0 += __shfl_xor_sync(0xffffffffu, sum0, 2);
    sum1 += __shfl_xor_sync(0xffffffffu, sum1, 1);
    sum1 += __shfl_xor_sync(0xffffffffu, sum1, 2);
    const float inv0 = 1.f / sum0;
    const float inv1 = 1.f / sum1;

    // ---- write P (fp16) — each warp writes/reads only its own 16 rows ----
    #pragma unroll
    for (int j = 0; j < 8; j++) {
        *reinterpret_cast<__half2*>(&smh[(APP >> 1) + r0 * 72 + j * 8 + 2 * tg]) =
            __floats2half2_rn(s[j][0] * inv0, s[j][1] * inv0);
        *reinterpret_cast<__half2*>(&smh[(APP >> 1) + (r0 + 8) * 72 + j * 8 + 2 * tg]) =
            __floats2half2_rn(s[j][2] * inv1, s[j][3] * inv1);
    }
    __syncwarp();

    // ---- PV (fp16) ----
    float o[4][4];
    #pragma unroll
    for (int n = 0; n < 4; n++)
        #pragma unroll
        for (int c = 0; c < 4; c++) o[n][c] = 0.f;

    #pragma unroll
    for (int kc = 0; kc < 4; kc++) {
        const uint32_t ks = kc * 32;
        uint32_t aP[4];
        ldsm_x4(aP, sb + APP + poffP + ks);
        #pragma unroll
        for (int n2 = 0; n2 < 2; n2++) {
            uint32_t bV[4];
            ldsm_x4(bV, sb + AVT + voffV[n2] + ks);
            mma_f16(o[2 * n2],     aP, bV[0], bV[1]);
            mma_f16(o[2 * n2 + 1], aP, bV[2], bV[3]);
        }
    }

    // ---- store fp16 for the proj GEMM ----
    if (r0 < NTOK) {
        __half* op = d_att + ((size_t)b * NTOK + r0) * DIM + h * HD;
        #pragma unroll
        for (int n = 0; n < 4; n++)
            *reinterpret_cast<__half2*>(&op[n * 8 + 2 * tg]) =
                __floats2half2_rn(o[n][0], o[n][1]);
    }
    if (r0 + 8 < NTOK) {
        __half* op = d_att + ((size_t)b * NTOK + r0 + 8) * DIM + h * HD;
        #pragma unroll
        for (int n = 0; n < 4; n++)
            *reinterpret_cast<__half2*>(&op[n * 8 + 2 * tg]) =
                __floats2half2_rn(o[n][2], o[n][3]);
    }
}

// ---------------- launch ----------------
extern "C" void kernel_launch(void* const* d_in, const int* in_sizes, int n_in,
                              void* d_out, int out_size)
{
    const float* x      = (const float*)d_in[0];
    const float* mask   = (const float*)d_in[1];
    const float* qkv_w  = (const float*)d_in[2];
    const float* qkv_b  = (const float*)d_in[3];
    const float* proj_w = (const float*)d_in[4];
    const float* proj_b = (const float*)d_in[5];
    const float* rpb    = (const float*)d_in[6];
    float* out          = (float*)d_out;

    cudaFuncSetAttribute(k_qkv,  cudaFuncAttributeMaxDynamicSharedMemorySize, SMEM_GEMM);
    cudaFuncSetAttribute(k_proj, cudaFuncAttributeMaxDynamicSharedMemorySize, SMEM_GEMM);

    __half *xh, *wqh, *wph;
    cudaGetSymbolAddress((void**)&xh,  d_xh);
    cudaGetSymbolAddress((void**)&wqh, d_wqh);
    cudaGetSymbolAddress((void**)&wph, d_wph);

    {
        int n4 = (MTOK * DIM) / 4;
        to_half<<<(n4 + 255) / 256, 256>>>(x, xh, n4);
        n4 = (QKVD * DIM) / 4;
        to_half<<<(n4 + 255) / 256, 256>>>(qkv_w, wqh, n4);
        n4 = (DIM * DIM) / 4;
        to_half<<<(n4 + 255) / 256, 256>>>(proj_w, wph, n4);
        const int total = NH * NWIN * 64 * 64;
        bm_kernel<<<(total + 255) / 256, 256>>>(rpb, mask);
    }

    {   // QKV: (55296 x 384) @ (1152 x 384)^T
        dim3 grid(QKVD / BN, MTOK / BM);
        k_qkv<<<grid, 256, SMEM_GEMM>>>(qkv_b);
    }

    attn_tc<<<B_ * NH, 128>>>();

    {   // proj: (55296 x 384) @ (384 x 384)^T
        dim3 grid(DIM / BN, MTOK / BM);
        k_proj<<<grid, 256, SMEM_GEMM>>>(proj_b, out);
    }
}

// round 12
// speedup vs baseline: 2.3657x; 1.2548x over previous
#include <cuda_runtime.h>
#include <cuda_fp16.h>
#include <math.h>
#include <stdint.h>

// ---------------- problem constants ----------------
#define B_      1024
#define NTOK    54
#define WIN     49
#define NP      5
#define NH      12
#define HD      32
#define DIM     384
#define QKVD    1152
#define NWIN    64
#define WH      7
#define WW      7
#define SCALE   0.17677669529663687f
#define MTOK    (B_*NTOK)       // 55296
#define KDIM    384

// ---------------- scratch ----------------
__device__ __half d_qkv[(size_t)MTOK * QKVD];    // fp16 qkv
__device__ __half d_att[(size_t)MTOK * DIM];     // fp16 attention output
__device__ __half d_xh[(size_t)MTOK * DIM];      // fp16 x
__device__ __half d_wqh[QKVD * DIM];             // fp16 qkv_w
__device__ __half d_wph[DIM * DIM];              // fp16 proj_w
__device__ __half d_bmh[NH * NWIN * 64 * 64];    // combined bias+mask, fp16

// ---------------- prepass: convert arrays to fp16 ----------------
__global__ void to_half(const float* __restrict__ in, __half* __restrict__ out, int n4) {
    int i = blockIdx.x * blockDim.x + threadIdx.x;
    if (i >= n4) return;
    float4 v = reinterpret_cast<const float4*>(in)[i];
    reinterpret_cast<__half2*>(out)[i * 2]     = __floats2half2_rn(v.x, v.y);
    reinterpret_cast<__half2*>(out)[i * 2 + 1] = __floats2half2_rn(v.z, v.w);
}

// ---------------- prepass: combined bias+mask table (fp16) ----------------
__global__ void bm_kernel(const float* __restrict__ rpb, const float* __restrict__ mask) {
    int idx = blockIdx.x * blockDim.x + threadIdx.x;
    const int total = NH * NWIN * 64 * 64;
    if (idx >= total) return;
    int c  = idx & 63;
    int r  = (idx >> 6) & 63;
    int wv = (idx >> 12) & 63;
    int h  = idx >> 18;
    float v = 0.f;
    if (r < NTOK) {
        if (c < NTOK) {
            if (r >= NP && c >= NP) {
                int i = r - NP, j = c - NP;
                int ih = i / WW, iw = i % WW;
                int jh = j / WW, jw = j % WW;
                int rpi = (ih - jh + WH - 1) * (2 * WW - 1) + (iw - jw + WW - 1);
                v = rpb[rpi * NH + h] + mask[wv * WIN * WIN + i * WIN + j];
            }
        } else {
            v = -60000.f;          // masked pad column (exp -> 0)
        }
    }
    d_bmh[idx] = __float2half_rn(v);
}

// ================= shared MMA/ldmatrix helpers =================
__device__ __forceinline__ void cp16(uint32_t smem, const __half* g) {
    asm volatile("cp.async.cg.shared.global [%0], [%1], 16;\n" :: "r"(smem), "l"(g));
}

__device__ __forceinline__ void ldsm_x4(uint32_t* r, uint32_t addr) {
    asm volatile("ldmatrix.sync.aligned.m8n8.x4.shared.b16 {%0,%1,%2,%3}, [%4];"
        : "=r"(r[0]), "=r"(r[1]), "=r"(r[2]), "=r"(r[3]) : "r"(addr));
}

__device__ __forceinline__ void ldsm_x4_t(uint32_t* r, uint32_t addr) {
    asm volatile("ldmatrix.sync.aligned.m8n8.x4.trans.shared.b16 {%0,%1,%2,%3}, [%4];"
        : "=r"(r[0]), "=r"(r[1]), "=r"(r[2]), "=r"(r[3]) : "r"(addr));
}

__device__ __forceinline__ void mma_f16(float* c, const uint32_t* a,
                                        uint32_t b0, uint32_t b1)
{
    asm volatile(
        "mma.sync.aligned.m16n8k16.row.col.f32.f16.f16.f32 "
        "{%0,%1,%2,%3}, {%4,%5,%6,%7}, {%8,%9}, {%0,%1,%2,%3};\n"
        : "+f"(c[0]), "+f"(c[1]), "+f"(c[2]), "+f"(c[3])
        : "r"(a[0]), "r"(a[1]), "r"(a[2]), "r"(a[3]), "r"(b0), "r"(b1));
}

// ================= fp16 mma.sync GEMM, BK=32, ldmatrix, 3-stage ==========
#define BM 128
#define BN 128
#define BK 32
#define RS 40                      // row stride in halfs (80 B)
#define ABYTES  (BM * RS * 2)      // 10240
#define STAGEB  (2 * ABYTES)       // 20480
#define SMEM_GEMM (3 * STAGEB)     // 61440

template<int N, bool HOUT>
__device__ __forceinline__ void tgemm_body(
    const __half* __restrict__ A, const __half* __restrict__ W,
    const float* __restrict__ bias, void* Cv, int K)
{
    extern __shared__ __align__(16) char smem[];

    const int tid  = threadIdx.x;
    const int warp = tid >> 5, lane = tid & 31;
    const int g    = lane >> 2, tg = lane & 3;
    const int wm   = warp & 1;
    const int wn   = warp >> 1;
    const int m0   = blockIdx.y * BM;
    const int n0   = blockIdx.x * BN;

    const int lr = tid >> 1;
    const int hk = (tid & 1) * 16;
    const __half* Ag = A + (size_t)(m0 + lr) * K + hk;
    const __half* Wg = W + (size_t)(n0 + lr) * K + hk;

    const uint32_t sbase = (uint32_t)__cvta_generic_to_shared(smem);
    const uint32_t poff  = (lr * RS + hk) * 2;

    const int l7  = lane & 7;
    const int lb3 = (lane >> 3) & 1;
    const int lb4 = lane >> 4;
    uint32_t aoffA[4], boffB[2];
    #pragma unroll
    for (int i = 0; i < 4; i++) {
        const int row = wm * 64 + i * 16 + l7 + 8 * lb3;
        aoffA[i] = (row * RS + 8 * lb4) * 2;
    }
    #pragma unroll
    for (int p = 0; p < 2; p++) {
        const int row = wn * 32 + p * 16 + l7 + 8 * lb4;
        boffB[p] = (row * RS + 8 * lb3) * 2;
    }

    float acc[4][4][4];
    #pragma unroll
    for (int i = 0; i < 4; i++)
        #pragma unroll
        for (int j = 0; j < 4; j++)
            #pragma unroll
            for (int c = 0; c < 4; c++) acc[i][j][c] = 0.f;

    const int nt = K / BK;

    #pragma unroll
    for (int p = 0; p < 2; p++) {
        const __half* ap = Ag + (size_t)p * BK;
        const __half* wp = Wg + (size_t)p * BK;
        const uint32_t sA = sbase + p * STAGEB + poff;
        const uint32_t sB = sA + ABYTES;
        cp16(sA, ap);       cp16(sA + 16, ap + 8);
        cp16(sB, wp);       cp16(sB + 16, wp + 8);
        asm volatile("cp.async.commit_group;\n");
    }

    int stage = 0;
    int nstage = 2;

    for (int t = 0; t < nt; t++) {
        if (t < nt - 1) asm volatile("cp.async.wait_group 1;\n");
        else            asm volatile("cp.async.wait_group 0;\n");
        __syncthreads();

        if (t + 2 < nt) {
            const __half* ap = Ag + (size_t)(t + 2) * BK;
            const __half* wp = Wg + (size_t)(t + 2) * BK;
            const uint32_t sA = sbase + nstage * STAGEB + poff;
            const uint32_t sB = sA + ABYTES;
            cp16(sA, ap);       cp16(sA + 16, ap + 8);
            cp16(sB, wp);       cp16(sB + 16, wp + 8);
            asm volatile("cp.async.commit_group;\n");
        }

        const uint32_t aS = sbase + stage * STAGEB;
        const uint32_t bS = aS + ABYTES;

        #pragma unroll
        for (int s = 0; s < 2; s++) {
            const uint32_t ks = s * 32;
            uint32_t af[4][4], bfr[4][2];
            #pragma unroll
            for (int i = 0; i < 4; i++)
                ldsm_x4(af[i], aS + aoffA[i] + ks);
            #pragma unroll
            for (int p = 0; p < 2; p++) {
                uint32_t br[4];
                ldsm_x4(br, bS + boffB[p] + ks);
                bfr[2 * p][0]     = br[0];  bfr[2 * p][1]     = br[1];
                bfr[2 * p + 1][0] = br[2];  bfr[2 * p + 1][1] = br[3];
            }
            #pragma unroll
            for (int i = 0; i < 4; i++)
                #pragma unroll
                for (int j = 0; j < 4; j++)
                    mma_f16(acc[i][j], af[i], bfr[j][0], bfr[j][1]);
        }

        stage  = (stage  == 2) ? 0 : stage  + 1;
        nstage = (nstage == 2) ? 0 : nstage + 1;
    }

    #pragma unroll
    for (int i = 0; i < 4; i++) {
        const int rb = m0 + wm * 64 + i * 16 + g;
        #pragma unroll
        for (int j = 0; j < 4; j++) {
            const int cb = n0 + wn * 32 + j * 8 + 2 * tg;
            const float b0v = bias[cb], b1v = bias[cb + 1];
            if (HOUT) {
                __half* C = (__half*)Cv;
                *reinterpret_cast<__half2*>(&C[(size_t)rb * N + cb]) =
                    __floats2half2_rn(acc[i][j][0] + b0v, acc[i][j][1] + b1v);
                *reinterpret_cast<__half2*>(&C[(size_t)(rb + 8) * N + cb]) =
                    __floats2half2_rn(acc[i][j][2] + b0v, acc[i][j][3] + b1v);
            } else {
                float* C = (float*)Cv;
                float2 v0, v1;
                v0.x = acc[i][j][0] + b0v;  v0.y = acc[i][j][1] + b1v;
                v1.x = acc[i][j][2] + b0v;  v1.y = acc[i][j][3] + b1v;
                *reinterpret_cast<float2*>(&C[(size_t)rb * N + cb])       = v0;
                *reinterpret_cast<float2*>(&C[(size_t)(rb + 8) * N + cb]) = v1;
            }
        }
    }
}

__global__ __launch_bounds__(256, 2) void k_qkv(const float* __restrict__ b)
{
    tgemm_body<QKVD, true>(d_xh, d_wqh, b, d_qkv, KDIM);
}

__global__ __launch_bounds__(256, 2) void k_proj(const float* __restrict__ b,
                                                 float* __restrict__ out)
{
    tgemm_body<DIM, false>(d_att, d_wph, b, out, KDIM);
}

// ================= fp16 attention: one block (128 thr) per (b,h) =========
// smem (bytes): Q[64][40]h @0, K @5120, V @10240, P[64][72]h @15360
#define AQ  0u
#define AK  5120u
#define AV  10240u
#define APP 15360u
#define ATT_SMEM (15360 + 9216)

__global__ __launch_bounds__(128) void attn_tc()
{
    __shared__ __align__(16) char smraw[ATT_SMEM];
    __half* smh = reinterpret_cast<__half*>(smraw);
    const uint32_t sb = (uint32_t)__cvta_generic_to_shared(smraw);

    const int b = blockIdx.x / NH;
    const int h = blockIdx.x % NH;
    const int tid = threadIdx.x;

    const __half* base = d_qkv + (size_t)b * NTOK * QKVD + h * HD;

    // zero pad rows 54..63 of Q,K,V (cols 0..31)
    for (int i = tid; i < 480; i += 128) {
        const int seg = i / 160;                 // 0..2
        const int rr  = 54 + (i / 16) % 10;
        const int cw  = i % 16;
        reinterpret_cast<uint32_t*>(smraw)[(seg * 5120 + rr * 80) / 4 + cw] = 0;
    }
    // cp.async the 54 valid rows (q,k,v: 64 B each = 4 x 16 B)
    for (int i = tid; i < 648; i += 128) {
        const int r   = i / 12;
        const int seg = (i % 12) / 4;
        const int ch  = i % 4;
        cp16(sb + seg * 5120 + r * 80 + ch * 16,
             base + r * QKVD + seg * DIM + ch * 8);
    }
    asm volatile("cp.async.commit_group;\n");
    asm volatile("cp.async.wait_group 0;\n");
    __syncthreads();

    const int w = tid >> 5, lane = tid & 31;
    const int g = lane >> 2, tg = lane & 3;
    const int r0 = w * 16 + g;

    const int l7  = lane & 7;
    const int lb3 = (lane >> 3) & 1;
    const int lb4 = lane >> 4;

    const uint32_t aoffQ = ((w * 16 + l7 + 8 * lb3) * 40 + 8 * lb4) * 2;
    uint32_t boffK[4];
    #pragma unroll
    for (int j2 = 0; j2 < 4; j2++)
        boffK[j2] = ((j2 * 16 + l7 + 8 * lb4) * 40 + 8 * lb3) * 2;
    const uint32_t poffP = ((w * 16 + l7 + 8 * lb3) * 72 + 8 * lb4) * 2;
    // V trans: lane group g2: row = (g2&1)*8 + l7, col-block = (g2>>1)*8
    const int g2 = lane >> 3;
    const uint32_t voffV = (((g2 & 1) * 8 + l7) * 40 + (g2 >> 1) * 8) * 2;

    // ---- QK^T (fp16, 16 MMAs) ----
    float s[8][4];
    #pragma unroll
    for (int j = 0; j < 8; j++)
        #pragma unroll
        for (int c = 0; c < 4; c++) s[j][c] = 0.f;

    #pragma unroll
    for (int kc = 0; kc < 2; kc++) {
        const uint32_t ks = kc * 32;
        uint32_t aQ[4];
        ldsm_x4(aQ, sb + AQ + aoffQ + ks);
        #pragma unroll
        for (int j2 = 0; j2 < 4; j2++) {
            uint32_t bK[4];
            ldsm_x4(bK, sb + AK + boffK[j2] + ks);
            mma_f16(s[2 * j2],     aQ, bK[0], bK[1]);
            mma_f16(s[2 * j2 + 1], aQ, bK[2], bK[3]);
        }
    }

    // ---- scale + bias + mask ----
    const __half* bmp = d_bmh + ((size_t)(h * NWIN + (b & (NWIN - 1)))) * 64 * 64;
    #pragma unroll
    for (int j = 0; j < 8; j++) {
        const float2 t0 = __half22float2(
            *reinterpret_cast<const __half2*>(&bmp[r0 * 64 + j * 8 + 2 * tg]));
        const float2 t1 = __half22float2(
            *reinterpret_cast<const __half2*>(&bmp[(r0 + 8) * 64 + j * 8 + 2 * tg]));
        s[j][0] = s[j][0] * SCALE + t0.x;
        s[j][1] = s[j][1] * SCALE + t0.y;
        s[j][2] = s[j][2] * SCALE + t1.x;
        s[j][3] = s[j][3] * SCALE + t1.y;
    }

    // ---- softmax ----
    float m0 = -1e30f, m1 = -1e30f;
    #pragma unroll
    for (int j = 0; j < 8; j++) {
        m0 = fmaxf(m0, fmaxf(s[j][0], s[j][1]));
        m1 = fmaxf(m1, fmaxf(s[j][2], s[j][3]));
    }
    m0 = fmaxf(m0, __shfl_xor_sync(0xffffffffu, m0, 1));
    m0 = fmaxf(m0, __shfl_xor_sync(0xffffffffu, m0, 2));
    m1 = fmaxf(m1, __shfl_xor_sync(0xffffffffu, m1, 1));
    m1 = fmaxf(m1, __shfl_xor_sync(0xffffffffu, m1, 2));

    float sum0 = 0.f, sum1 = 0.f;
    #pragma unroll
    for (int j = 0; j < 8; j++) {
        s[j][0] = __expf(s[j][0] - m0);
        s[j][1] = __expf(s[j][1] - m0);
        s[j][2] = __expf(s[j][2] - m1);
        s[j][3] = __expf(s[j][3] - m1);
        sum0 += s[j][0] + s[j][1];
        sum1 += s[j][2] + s[j][3];
    }
    sum0 += __shfl_xor_sync(0xffffffffu, sum0, 1);
    sum0 += __shfl_xor_sync(0xffffffffu, sum0, 2);
    sum1 += __shfl_xor_sync(0xffffffffu, sum1, 1);
    sum1 += __shfl_xor_sync(0xffffffffu, sum1, 2);
    const float inv0 = 1.f / sum0;
    const float inv1 = 1.f / sum1;

    // ---- write P (fp16) — each warp writes/reads only its own 16 rows ----
    #pragma unroll
    for (int j = 0; j < 8; j++) {
        *reinterpret_cast<__half2*>(&smh[(APP >> 1) + r0 * 72 + j * 8 + 2 * tg]) =
            __floats2half2_rn(s[j][0] * inv0, s[j][1] * inv0);
        *reinterpret_cast<__half2*>(&smh[(APP >> 1) + (r0 + 8) * 72 + j * 8 + 2 * tg]) =
            __floats2half2_rn(s[j][2] * inv1, s[j][3] * inv1);
    }
    __syncwarp();

    // ---- PV (fp16, V via ldmatrix.trans) ----
    float o[4][4];
    #pragma unroll
    for (int n = 0; n < 4; n++)
        #pragma unroll
        for (int c = 0; c < 4; c++) o[n][c] = 0.f;

    #pragma unroll
    for (int kc = 0; kc < 4; kc++) {
        uint32_t aP[4];
        ldsm_x4(aP, sb + APP + poffP + kc * 32);
        #pragma unroll
        for (int nh = 0; nh < 2; nh++) {
            uint32_t bV[4];
            ldsm_x4_t(bV, sb + AV + voffV + nh * 32 + kc * 1280);
            mma_f16(o[2 * nh],     aP, bV[0], bV[1]);
            mma_f16(o[2 * nh + 1], aP, bV[2], bV[3]);
        }
    }

    // ---- store fp16 for the proj GEMM ----
    if (r0 < NTOK) {
        __half* op = d_att + ((size_t)b * NTOK + r0) * DIM + h * HD;
        #pragma unroll
        for (int n = 0; n < 4; n++)
            *reinterpret_cast<__half2*>(&op[n * 8 + 2 * tg]) =
                __floats2half2_rn(o[n][0], o[n][1]);
    }
    if (r0 + 8 < NTOK) {
        __half* op = d_att + ((size_t)b * NTOK + r0 + 8) * DIM + h * HD;
        #pragma unroll
        for (int n = 0; n < 4; n++)
            *reinterpret_cast<__half2*>(&op[n * 8 + 2 * tg]) =
                __floats2half2_rn(o[n][2], o[n][3]);
    }
}

// ---------------- launch ----------------
extern "C" void kernel_launch(void* const* d_in, const int* in_sizes, int n_in,
                              void* d_out, int out_size)
{
    const float* x      = (const float*)d_in[0];
    const float* mask   = (const float*)d_in[1];
    const float* qkv_w  = (const float*)d_in[2];
    const float* qkv_b  = (const float*)d_in[3];
    const float* proj_w = (const float*)d_in[4];
    const float* proj_b = (const float*)d_in[5];
    const float* rpb    = (const float*)d_in[6];
    float* out          = (float*)d_out;

    cudaFuncSetAttribute(k_qkv,  cudaFuncAttributeMaxDynamicSharedMemorySize, SMEM_GEMM);
    cudaFuncSetAttribute(k_proj, cudaFuncAttributeMaxDynamicSharedMemorySize, SMEM_GEMM);

    __half *xh, *wqh, *wph;
    cudaGetSymbolAddress((void**)&xh,  d_xh);
    cudaGetSymbolAddress((void**)&wqh, d_wqh);
    cudaGetSymbolAddress((void**)&wph, d_wph);

    {
        int n4 = (MTOK * DIM) / 4;
        to_half<<<(n4 + 255) / 256, 256>>>(x, xh, n4);
        n4 = (QKVD * DIM) / 4;
        to_half<<<(n4 + 255) / 256, 256>>>(qkv_w, wqh, n4);
        n4 = (DIM * DIM) / 4;
        to_half<<<(n4 + 255) / 256, 256>>>(proj_w, wph, n4);
        const int total = NH * NWIN * 64 * 64;
        bm_kernel<<<(total + 255) / 256, 256>>>(rpb, mask);
    }

    {   // QKV: (55296 x 384) @ (1152 x 384)^T -> fp16
        dim3 grid(QKVD / BN, MTOK / BM);
        k_qkv<<<grid, 256, SMEM_GEMM>>>(qkv_b);
    }

    attn_tc<<<B_ * NH, 128>>>();

    {   // proj: (55296 x 384) @ (384 x 384)^T -> fp32 out
        dim3 grid(DIM / BN, MTOK / BM);
        k_proj<<<grid, 256, SMEM_GEMM>>>(proj_b, out);
    }
}